// round 10
// baseline (speedup 1.0000x reference)
#include <cuda_runtime.h>
#include <cuda_bf16.h>
#include <math.h>
#include <stdint.h>

#define B_    8
#define SP    128
#define ST    64
#define SV    64
#define SEQ   256
#define DMODEL 768
#define DLLM  4096
#define NH    32
#define HD    128
#define DFF   11008
#define NTOK  (B_*SEQ)
#define QKVS  (3*DLLM)
#define GUS   (2*DFF)
#define EPS   1e-5f
#define GEMM_GRID 296

// ---------------- fp32 scratch ----------------
#define SZ_TOKD ((size_t)NTOK*DLLM)
#define SZ_FF   ((size_t)NTOK*DFF)
#define OFF_H    ((size_t)0)
#define OFF_XN   (SZ_TOKD)
#define OFF_QKV  (2*SZ_TOKD)
#define OFF_GU   (5*SZ_TOKD)
#define OFF_COS  (OFF_GU + 2*SZ_FF)
#define OFF_SIN  (OFF_COS + (size_t)SEQ*64)
#define OFF_POOL (OFF_SIN + (size_t)SEQ*64)
#define OFF_Y1   (OFF_POOL + (size_t)B_*DLLM)
#define SCRATCH_TOTAL (OFF_Y1 + (size_t)B_*768)
__device__ float g_scratch[SCRATCH_TOTAL];

// ---------------- bf16 scratch ----------------
#define W4 ((size_t)DLLM*DLLM)
#define WF ((size_t)DLLM*DFF)
#define SZ_TV  ((size_t)512*DMODEL)
#define SZ_INW ((size_t)DMODEL*DLLM)
#define BO_XNH  ((size_t)0)
#define BO_XNL  (BO_XNH + SZ_TOKD)
#define BO_ATH  (BO_XNL + SZ_TOKD)
#define BO_ATL  (BO_ATH + SZ_TOKD)
#define BO_GH   (BO_ATL + SZ_TOKD)
#define BO_GL   (BO_GH + SZ_FF)
#define BO_TXH  (BO_GL + SZ_FF)
#define BO_TXL  (BO_TXH + SZ_TV)
#define BO_VXH  (BO_TXL + SZ_TV)
#define BO_VXL  (BO_VXH + SZ_TV)
#define BO_INWH (BO_VXL + SZ_TV)
#define BO_INWL (BO_INWH + SZ_INW)
#define BO_QKVH (BO_INWL + SZ_INW)
#define BO_QKVL (BO_QKVH + 6*W4)
#define BO_OH   (BO_QKVL + 6*W4)
#define BO_OL   (BO_OH + 2*W4)
#define BO_GUH  (BO_OL + 2*W4)
#define BO_GUL  (BO_GUH + 4*WF)
#define BO_DWH  (BO_GUL + 4*WF)
#define BO_DWL  (BO_DWH + 2*WF)
#define BF_TOTAL (BO_DWL + 2*WF)
__device__ __align__(256) __nv_bfloat16 g_bf[BF_TOTAL];

// ---------------- helpers ----------------
__device__ __forceinline__ uint32_t smem_u32(const void* p) {
    uint32_t a;
    asm("{ .reg .u64 t; cvta.to.shared.u64 t, %1; cvt.u32.u64 %0, t; }" : "=r"(a) : "l"(p));
    return a;
}
__device__ __forceinline__ void cp16(uint32_t d, const void* s) {
    asm volatile("cp.async.cg.shared.global [%0], [%1], 16;" :: "r"(d), "l"(s));
}
__device__ __forceinline__ void split_bf(float x, __nv_bfloat16& h, __nv_bfloat16& l) {
    h = __float2bfloat16_rn(x);
    l = __float2bfloat16_rn(x - __bfloat162float(h));
}
__device__ __forceinline__ void mma_bf16(float* c,
    uint32_t a0, uint32_t a1, uint32_t a2, uint32_t a3, uint32_t b0, uint32_t b1) {
    asm volatile(
        "mma.sync.aligned.m16n8k16.row.col.f32.bf16.bf16.f32 "
        "{%0,%1,%2,%3}, {%4,%5,%6,%7}, {%8,%9}, {%0,%1,%2,%3};"
        : "+f"(c[0]), "+f"(c[1]), "+f"(c[2]), "+f"(c[3])
        : "r"(a0), "r"(a1), "r"(a2), "r"(a3), "r"(b0), "r"(b1));
}
__device__ __forceinline__ void ldm_x4(uint32_t& r0, uint32_t& r1,
                                       uint32_t& r2, uint32_t& r3, uint32_t a) {
    asm volatile("ldmatrix.sync.aligned.m8n8.x4.shared.b16 {%0,%1,%2,%3}, [%4];"
        : "=r"(r0), "=r"(r1), "=r"(r2), "=r"(r3) : "r"(a));
}

// ---------------------------------------------------------------------------
// Persistent bf16-split GEMM via mma.sync + ldmatrix. BM=128, BN=64, BK=32.
// C[M,N] = A[M,K] @ W[K,N]; A=Ah+Al [M,K] bf16; W^T=Bh+Bl [N,K] bf16.
// 3 passes AhBh + AhBl + AlBh, fp32 accum, 3-stage cp.async, 2 CTAs/SM.
// Grid = GEMM_GRID persistent CTAs looping over tiles (no wave quantization).
// flags: 1 accumulate, 2 bias, 4 row remap. M%128==0, N%64==0, K%32==0.
// ---------------------------------------------------------------------------
#define TPITCH 40
#define O_AH 0
#define O_AL (128*TPITCH)
#define O_BH (256*TPITCH)
#define O_BL (320*TPITCH)
#define STAGE_E (384*TPITCH)
#define GSMEM_BYTES (3*STAGE_E*2)

__global__ __launch_bounds__(256, 2) void gemm_tc(
    const __nv_bfloat16* __restrict__ Ah, const __nv_bfloat16* __restrict__ Al,
    const __nv_bfloat16* __restrict__ Bh, const __nv_bfloat16* __restrict__ Bl,
    float* __restrict__ C, int M, int N, int K,
    int flags, const float* __restrict__ bias, int map_base,
    int tilesX, int ntiles)
{
    extern __shared__ __nv_bfloat16 sm[];
    const int tid = threadIdx.x;
    const int wid = tid >> 5, lane = tid & 31;
    const int wm = wid & 3, wn = wid >> 2;
    const int gr = lane >> 2, qc = lane & 3;
    const uint32_t smbase = smem_u32(sm);

    const uint32_t aoff = (uint32_t)(((wm * 32 + (lane & 15)) * TPITCH + ((lane >> 4) << 3)) * 2);
    const uint32_t boff = (uint32_t)(((wn * 32 + ((lane >> 4) << 3) + (lane & 7)) * TPITCH
                                      + (((lane >> 3) & 1) << 3)) * 2);

    // Tile-invariant loader metadata: 1536 16B chunks / stage, 6 per thread
    const __nv_bfloat16* lbase[6];
    int lrow[6], lsub[6], lisA[6];
    uint32_t soff[6];
#pragma unroll
    for (int i = 0; i < 6; i++) {
        int c = tid + i * 256;
        int tb;
        if (c < 512)       { lbase[i] = Ah; lrow[i] = c >> 2;          tb = O_AH; lisA[i] = 1; }
        else if (c < 1024) { lbase[i] = Al; lrow[i] = (c - 512) >> 2;  tb = O_AL; lisA[i] = 1; }
        else if (c < 1280) { lbase[i] = Bh; lrow[i] = (c - 1024) >> 2; tb = O_BH; lisA[i] = 0; }
        else               { lbase[i] = Bl; lrow[i] = (c - 1280) >> 2; tb = O_BL; lisA[i] = 0; }
        lsub[i] = c & 3;
        soff[i] = (uint32_t)((tb + lrow[i] * TPITCH + lsub[i] * 8) * 2);
    }

    const int S = K / 32;

    for (int tile = blockIdx.x; tile < ntiles; tile += gridDim.x) {
        const int m0 = (tile / tilesX) * 128;
        const int n0 = (tile % tilesX) * 64;

        const __nv_bfloat16* gp[6];
#pragma unroll
        for (int i = 0; i < 6; i++)
            gp[i] = lbase[i] + (size_t)((lisA[i] ? m0 : n0) + lrow[i]) * K + lsub[i] * 8;

#define LOAD_STAGE(s_) do { \
    uint32_t sb_ = smbase + (uint32_t)(((s_) % 3) * STAGE_E * 2); \
    _Pragma("unroll") \
    for (int i_ = 0; i_ < 6; i_++) \
        cp16(sb_ + soff[i_], gp[i_] + (size_t)(s_) * 32); \
    asm volatile("cp.async.commit_group;" ::: "memory"); \
} while (0)

        LOAD_STAGE(0);
        LOAD_STAGE(1);

        float acc[2][4][4];
#pragma unroll
        for (int t = 0; t < 2; t++)
#pragma unroll
            for (int n = 0; n < 4; n++)
#pragma unroll
                for (int e = 0; e < 4; e++) acc[t][n][e] = 0.f;

        for (int s = 0; s < S; s++) {
            asm volatile("cp.async.wait_group 1;" ::: "memory");
            __syncthreads();
            if (s + 2 < S) { LOAD_STAGE(s + 2); }
            else { asm volatile("cp.async.commit_group;" ::: "memory"); }

            const uint32_t stg = smbase + (uint32_t)((s % 3) * STAGE_E * 2);

#pragma unroll
            for (int kk = 0; kk < 32; kk += 16) {
                uint32_t ah[2][4], al[2][4], bh[4][2], bl[4][2];
#pragma unroll
                for (int t = 0; t < 2; t++) {
                    uint32_t off = aoff + (uint32_t)((t * 16 * TPITCH + kk) * 2);
                    ldm_x4(ah[t][0], ah[t][1], ah[t][2], ah[t][3], stg + O_AH * 2 + off);
                    ldm_x4(al[t][0], al[t][1], al[t][2], al[t][3], stg + O_AL * 2 + off);
                }
#pragma unroll
                for (int j = 0; j < 2; j++) {
                    uint32_t off = boff + (uint32_t)((j * 16 * TPITCH + kk) * 2);
                    ldm_x4(bh[2*j][0], bh[2*j][1], bh[2*j+1][0], bh[2*j+1][1], stg + O_BH * 2 + off);
                    ldm_x4(bl[2*j][0], bl[2*j][1], bl[2*j+1][0], bl[2*j+1][1], stg + O_BL * 2 + off);
                }
#pragma unroll
                for (int t = 0; t < 2; t++)
#pragma unroll
                    for (int n = 0; n < 4; n++) {
                        mma_bf16(acc[t][n], ah[t][0], ah[t][1], ah[t][2], ah[t][3],
                                 bh[n][0], bh[n][1]);
                        mma_bf16(acc[t][n], ah[t][0], ah[t][1], ah[t][2], ah[t][3],
                                 bl[n][0], bl[n][1]);
                        mma_bf16(acc[t][n], al[t][0], al[t][1], al[t][2], al[t][3],
                                 bh[n][0], bh[n][1]);
                    }
            }
        }

        // Epilogue
#pragma unroll
        for (int t = 0; t < 2; t++) {
#pragma unroll
            for (int half = 0; half < 2; half++) {
                int grow = m0 + wm * 32 + t * 16 + gr + half * 8;
                int orow = (flags & 4) ? ((grow >> 6) * SEQ + map_base + (grow & 63)) : grow;
                float* crow = C + (size_t)orow * N;
#pragma unroll
                for (int n = 0; n < 4; n++) {
                    int col = n0 + wn * 32 + n * 8 + qc * 2;
                    float2 v;
                    v.x = acc[t][n][half * 2 + 0];
                    v.y = acc[t][n][half * 2 + 1];
                    if (flags & 2) {
                        float2 b2 = *reinterpret_cast<const float2*>(bias + col);
                        v.x += b2.x; v.y += b2.y;
                    }
                    if (flags & 1) {
                        float2 o = *reinterpret_cast<const float2*>(crow + col);
                        v.x += o.x; v.y += o.y;
                    }
                    *reinterpret_cast<float2*>(crow + col) = v;
                }
            }
        }
        asm volatile("cp.async.wait_group 0;" ::: "memory");
        __syncthreads();
#undef LOAD_STAGE
    }
}

// ---------------- transpose + split: src[K,N] fp32 -> [N,K] bf16 hi/lo ------
// 64(k) x 32(n) tile; __nv_bfloat162 writes give 128B store segments.
// grid (N/32, K/64), block (32,8).
__global__ void transpose_split_kernel(
    const float* __restrict__ src,
    __nv_bfloat16* __restrict__ dhi, __nv_bfloat16* __restrict__ dlo,
    int K, int N)
{
    __shared__ float tile[64][33];
    const int n0 = blockIdx.x * 32, k0 = blockIdx.y * 64;
    const int tx = threadIdx.x, ty = threadIdx.y;
#pragma unroll
    for (int i = 0; i < 64; i += 8)
        tile[ty + i][tx] = src[(size_t)(k0 + ty + i) * N + n0 + tx];
    __syncthreads();
#pragma unroll
    for (int j = 0; j < 32; j += 8) {
        int nrow = ty + j;
        float v0 = tile[2 * tx][nrow];
        float v1 = tile[2 * tx + 1][nrow];
        __nv_bfloat16 h0, l0, h1, l1;
        split_bf(v0, h0, l0);
        split_bf(v1, h1, l1);
        size_t idx = (size_t)(n0 + nrow) * K + k0 + 2 * tx;
        *reinterpret_cast<__nv_bfloat162*>(dhi + idx) = __nv_bfloat162(h0, h1);
        *reinterpret_cast<__nv_bfloat162*>(dlo + idx) = __nv_bfloat162(l0, l1);
    }
}

__global__ void split_kernel(const float* __restrict__ src,
                             __nv_bfloat16* __restrict__ hi,
                             __nv_bfloat16* __restrict__ lo, size_t n)
{
    size_t idx = (size_t)blockIdx.x * blockDim.x + threadIdx.x;
    if (idx >= n) return;
    __nv_bfloat16 h, l;
    split_bf(src[idx], h, l);
    hi[idx] = h; lo[idx] = l;
}

__global__ void rope_table_kernel(float* __restrict__ cosb, float* __restrict__ sinb)
{
    int idx = blockIdx.x * blockDim.x + threadIdx.x;
    if (idx >= SEQ * 64) return;
    int s = idx >> 6, i = idx & 63;
    double inv = exp(-((double)(2 * i) / 128.0) * log(10000.0));
    double ang = (double)s * inv;
    cosb[idx] = (float)cos(ang);
    sinb[idx] = (float)sin(ang);
}

__global__ void embed_gather_kernel(const int* __restrict__ ids,
                                    const float* __restrict__ table,
                                    float* __restrict__ h)
{
    int idx = blockIdx.x * blockDim.x + threadIdx.x;
    if (idx >= B_ * SP * DLLM) return;
    int d = idx & (DLLM - 1);
    int r = (idx >> 12) & (SP - 1);
    int b = idx >> 19;
    int id = ids[b * SP + r];
    h[((size_t)(b * SEQ + r)) * DLLM + d] = table[(size_t)id * DLLM + d];
}

__global__ __launch_bounds__(256) void rmsnorm_kernel(
    const float* __restrict__ x, const float* __restrict__ w, float* __restrict__ out)
{
    int t = blockIdx.x;
    const float4* xr = reinterpret_cast<const float4*>(x + (size_t)t * DLLM);
    float4 vals[4];
    float s = 0.f;
#pragma unroll
    for (int j = 0; j < 4; j++) {
        float4 v = xr[threadIdx.x + j * 256];
        vals[j] = v;
        s += v.x * v.x + v.y * v.y + v.z * v.z + v.w * v.w;
    }
#pragma unroll
    for (int off = 16; off > 0; off >>= 1) s += __shfl_xor_sync(0xffffffffu, s, off);
    __shared__ float red[8];
    __shared__ float sscale;
    if ((threadIdx.x & 31) == 0) red[threadIdx.x >> 5] = s;
    __syncthreads();
    if (threadIdx.x == 0) {
        float r = 0.f;
#pragma unroll
        for (int i = 0; i < 8; i++) r += red[i];
        sscale = rsqrtf(r * (1.0f / DLLM) + EPS);
    }
    __syncthreads();
    float sc = sscale;
    const float4* w4 = reinterpret_cast<const float4*>(w);
    float4* o4 = reinterpret_cast<float4*>(out + (size_t)t * DLLM);
#pragma unroll
    for (int j = 0; j < 4; j++) {
        float4 v = vals[j];
        float4 wv = w4[threadIdx.x + j * 256];
        o4[threadIdx.x + j * 256] = make_float4(
            v.x * sc * wv.x, v.y * sc * wv.y, v.z * sc * wv.z, v.w * sc * wv.w);
    }
}

__global__ __launch_bounds__(256) void rmsnorm_split_kernel(
    const float* __restrict__ x, const float* __restrict__ w,
    __nv_bfloat16* __restrict__ ohi, __nv_bfloat16* __restrict__ olo)
{
    int t = blockIdx.x;
    const float4* xr = reinterpret_cast<const float4*>(x + (size_t)t * DLLM);
    float4 vals[4];
    float s = 0.f;
#pragma unroll
    for (int j = 0; j < 4; j++) {
        float4 v = xr[threadIdx.x + j * 256];
        vals[j] = v;
        s += v.x * v.x + v.y * v.y + v.z * v.z + v.w * v.w;
    }
#pragma unroll
    for (int off = 16; off > 0; off >>= 1) s += __shfl_xor_sync(0xffffffffu, s, off);
    __shared__ float red[8];
    __shared__ float sscale;
    if ((threadIdx.x & 31) == 0) red[threadIdx.x >> 5] = s;
    __syncthreads();
    if (threadIdx.x == 0) {
        float r = 0.f;
#pragma unroll
        for (int i = 0; i < 8; i++) r += red[i];
        sscale = rsqrtf(r * (1.0f / DLLM) + EPS);
    }
    __syncthreads();
    float sc = sscale;
    const float4* w4 = reinterpret_cast<const float4*>(w);
    size_t base = (size_t)t * DLLM;
#pragma unroll
    for (int j = 0; j < 4; j++) {
        float4 v = vals[j];
        float4 wv = w4[threadIdx.x + j * 256];
        float rr[4] = { v.x * sc * wv.x, v.y * sc * wv.y, v.z * sc * wv.z, v.w * sc * wv.w };
        size_t o = base + ((size_t)threadIdx.x + j * 256) * 4;
#pragma unroll
        for (int e = 0; e < 4; e++) {
            __nv_bfloat16 h, l;
            split_bf(rr[e], h, l);
            ohi[o + e] = h; olo[o + e] = l;
        }
    }
}

__global__ void rope_apply_kernel(float* __restrict__ qkv,
                                  const float* __restrict__ cosb,
                                  const float* __restrict__ sinb)
{
    int idx = blockIdx.x * blockDim.x + threadIdx.x;
    if (idx >= NTOK * NH * 64) return;
    int i = idx & 63;
    int h = (idx >> 6) & (NH - 1);
    int t = idx >> 11;
    int s = t & (SEQ - 1);
    float c = cosb[s * 64 + i];
    float sn = sinb[s * 64 + i];
    size_t base = (size_t)t * QKVS + h * HD + i;
    float x1 = qkv[base], x2 = qkv[base + 64];
    qkv[base]      = x1 * c - x2 * sn;
    qkv[base + 64] = x2 * c + x1 * sn;
    size_t kb = base + DLLM;
    x1 = qkv[kb]; x2 = qkv[kb + 64];
    qkv[kb]      = x1 * c - x2 * sn;
    qkv[kb + 64] = x2 * c + x1 * sn;
}

__global__ __launch_bounds__(256) void attention_kernel(
    const float* __restrict__ qkv,
    __nv_bfloat16* __restrict__ ohi, __nv_bfloat16* __restrict__ olo)
{
    __shared__ float sc[8][SEQ];
    const int b = blockIdx.z, hh = blockIdx.y;
    const int w = threadIdx.x >> 5, lane = threadIdx.x & 31;
    const int qi = blockIdx.x * 8 + w;
    const float scale = 0.088388347648318447f;

    const float* qrow = qkv + (size_t)(b * SEQ + qi) * QKVS + hh * HD;
    float4 qv = reinterpret_cast<const float4*>(qrow)[lane];

    const float* kbase = qkv + (size_t)b * SEQ * QKVS + DLLM + hh * HD;
    for (int kk = 0; kk <= qi; kk++) {
        float4 kv = reinterpret_cast<const float4*>(kbase + (size_t)kk * QKVS)[lane];
        float d = qv.x * kv.x + qv.y * kv.y + qv.z * kv.z + qv.w * kv.w;
#pragma unroll
        for (int off = 16; off > 0; off >>= 1) d += __shfl_xor_sync(0xffffffffu, d, off);
        if (lane == 0) sc[w][kk] = d * scale;
    }
    __syncwarp();

    float m = -1e30f;
    for (int kk = lane; kk <= qi; kk += 32) m = fmaxf(m, sc[w][kk]);
#pragma unroll
    for (int off = 16; off > 0; off >>= 1) m = fmaxf(m, __shfl_xor_sync(0xffffffffu, m, off));

    float ssum = 0.f;
    for (int kk = lane; kk <= qi; kk += 32) {
        float p = expf(sc[w][kk] - m);
        sc[w][kk] = p;
        ssum += p;
    }
#pragma unroll
    for (int off = 16; off > 0; off >>= 1) ssum += __shfl_xor_sync(0xffffffffu, ssum, off);
    __syncwarp();
    float inv = 1.0f / ssum;

    const float* vbase = qkv + (size_t)b * SEQ * QKVS + 2 * DLLM + hh * HD;
    float4 acc = make_float4(0.f, 0.f, 0.f, 0.f);
    for (int kk = 0; kk <= qi; kk++) {
        float p = sc[w][kk];
        float4 vv = reinterpret_cast<const float4*>(vbase + (size_t)kk * QKVS)[lane];
        acc.x += p * vv.x; acc.y += p * vv.y;
        acc.z += p * vv.z; acc.w += p * vv.w;
    }
    size_t o = (size_t)(b * SEQ + qi) * DLLM + hh * HD + lane * 4;
    float r[4] = { acc.x * inv, acc.y * inv, acc.z * inv, acc.w * inv };
#pragma unroll
    for (int e = 0; e < 4; e++) {
        __nv_bfloat16 h, l;
        split_bf(r[e], h, l);
        ohi[o + e] = h; olo[o + e] = l;
    }
}

__global__ void silu_mul_split_kernel(const float* __restrict__ gu,
                                      __nv_bfloat16* __restrict__ ohi,
                                      __nv_bfloat16* __restrict__ olo)
{
    int j = blockIdx.x * 256 + threadIdx.x;
    int t = blockIdx.y;
    const float* row = gu + (size_t)t * GUS;
    float x = row[j];
    float r = (x / (1.0f + expf(-x))) * row[DFF + j];
    __nv_bfloat16 h, l;
    split_bf(r, h, l);
    size_t o = (size_t)t * DFF + j;
    ohi[o] = h; olo[o] = l;
}

__global__ void pool_kernel(const float* __restrict__ xn, float* __restrict__ pooled)
{
    int idx = blockIdx.x * blockDim.x + threadIdx.x;
    if (idx >= B_ * DLLM) return;
    int b = idx >> 12, d = idx & (DLLM - 1);
    float s = 0.f;
    for (int t = 0; t < SEQ; t++)
        s += xn[(size_t)(b * SEQ + t) * DLLM + d];
    pooled[idx] = s * (1.0f / SEQ);
}

__global__ void head1_kernel(const float* __restrict__ pooled,
                             const float* __restrict__ W,
                             const float* __restrict__ bias,
                             float* __restrict__ y1)
{
    int b = blockIdx.x, j = threadIdx.x;
    const float* p = pooled + (size_t)b * DLLM;
    float s = bias[j];
    for (int i = 0; i < DLLM; i++) s += p[i] * W[(size_t)i * 768 + j];
    y1[b * 768 + j] = s;
}

__global__ void head2_kernel(const float* __restrict__ y1,
                             const float* __restrict__ W,
                             const float* __restrict__ bias,
                             float* __restrict__ out)
{
    int b = blockIdx.x;
    float s = 0.f;
    for (int j = threadIdx.x; j < 768; j += 256) s += y1[b * 768 + j] * W[j];
#pragma unroll
    for (int off = 16; off > 0; off >>= 1) s += __shfl_xor_sync(0xffffffffu, s, off);
    __shared__ float red[8];
    if ((threadIdx.x & 31) == 0) red[threadIdx.x >> 5] = s;
    __syncthreads();
    if (threadIdx.x == 0) {
        float r = 0.f;
#pragma unroll
        for (int i = 0; i < 8; i++) r += red[i];
        out[b] = r + bias[0];
    }
}

// ---------------------------------------------------------------------------
static inline void launch_gemm(const __nv_bfloat16* Ah, const __nv_bfloat16* Al,
                               const __nv_bfloat16* Bh, const __nv_bfloat16* Bl,
                               float* C, int M, int N, int K,
                               int flags, const float* bias, int map_base)
{
    int tilesX = N / 64;
    int ntiles = tilesX * (M / 128);
    gemm_tc<<<GEMM_GRID, 256, GSMEM_BYTES>>>(Ah, Al, Bh, Bl, C, M, N, K,
                                             flags, bias, map_base, tilesX, ntiles);
}

extern "C" void kernel_launch(void* const* d_in, const int* in_sizes, int n_in,
                              void* d_out, int out_size)
{
    const float* text  = (const float*)d_in[0];
    const float* vis   = (const float*)d_in[1];
    const int*   ids   = (const int*)  d_in[2];
    const float* inW   = (const float*)d_in[3];
    const float* inb   = (const float*)d_in[4];
    const float* etab  = (const float*)d_in[5];
    const float* Wq    = (const float*)d_in[6];
    const float* Wk    = (const float*)d_in[7];
    const float* Wv    = (const float*)d_in[8];
    const float* Wo    = (const float*)d_in[9];
    const float* ln1   = (const float*)d_in[10];
    const float* ln2   = (const float*)d_in[11];
    const float* Wg    = (const float*)d_in[12];
    const float* Wu    = (const float*)d_in[13];
    const float* Wd    = (const float*)d_in[14];
    const float* fnw   = (const float*)d_in[15];
    const float* o1W   = (const float*)d_in[16];
    const float* o1b   = (const float*)d_in[17];
    const float* o2W   = (const float*)d_in[18];
    const float* o2b   = (const float*)d_in[19];
    float* out = (float*)d_out;

    cudaFuncSetAttribute(gemm_tc, cudaFuncAttributeMaxDynamicSharedMemorySize,
                         GSMEM_BYTES);

    float* S = nullptr;
    cudaGetSymbolAddress((void**)&S, g_scratch);
    __nv_bfloat16* BS = nullptr;
    cudaGetSymbolAddress((void**)&BS, g_bf);

    float* h    = S + OFF_H;
    float* xn   = S + OFF_XN;
    float* qkv  = S + OFF_QKV;
    float* gu   = S + OFF_GU;
    float* cosb = S + OFF_COS;
    float* sinb = S + OFF_SIN;
    float* pooled = S + OFF_POOL;
    float* y1   = S + OFF_Y1;

    __nv_bfloat16 *xnh = BS + BO_XNH, *xnl = BS + BO_XNL;
    __nv_bfloat16 *ath = BS + BO_ATH, *atl = BS + BO_ATL;
    __nv_bfloat16 *gh  = BS + BO_GH,  *gl  = BS + BO_GL;
    __nv_bfloat16 *txh = BS + BO_TXH, *txl = BS + BO_TXL;
    __nv_bfloat16 *vxh = BS + BO_VXH, *vxl = BS + BO_VXL;
    __nv_bfloat16 *inwh = BS + BO_INWH, *inwl = BS + BO_INWL;

    dim3 t32(32, 8);

    rope_table_kernel<<<(SEQ * 64 + 255) / 256, 256>>>(cosb, sinb);

    transpose_split_kernel<<<dim3(DLLM / 32, DMODEL / 64), t32>>>(inW, inwh, inwl, DMODEL, DLLM);
    for (int l = 0; l < 2; l++) {
        transpose_split_kernel<<<dim3(DLLM / 32, DLLM / 64), t32>>>(
            Wq + (size_t)l * W4, BS + BO_QKVH + (size_t)l * 3 * W4,
            BS + BO_QKVL + (size_t)l * 3 * W4, DLLM, DLLM);
        transpose_split_kernel<<<dim3(DLLM / 32, DLLM / 64), t32>>>(
            Wk + (size_t)l * W4, BS + BO_QKVH + (size_t)l * 3 * W4 + W4,
            BS + BO_QKVL + (size_t)l * 3 * W4 + W4, DLLM, DLLM);
        transpose_split_kernel<<<dim3(DLLM / 32, DLLM / 64), t32>>>(
            Wv + (size_t)l * W4, BS + BO_QKVH + (size_t)l * 3 * W4 + 2 * W4,
            BS + BO_QKVL + (size_t)l * 3 * W4 + 2 * W4, DLLM, DLLM);
        transpose_split_kernel<<<dim3(DLLM / 32, DLLM / 64), t32>>>(
            Wo + (size_t)l * W4, BS + BO_OH + (size_t)l * W4,
            BS + BO_OL + (size_t)l * W4, DLLM, DLLM);
        transpose_split_kernel<<<dim3(DFF / 32, DLLM / 64), t32>>>(
            Wg + (size_t)l * WF, BS + BO_GUH + (size_t)l * 2 * WF,
            BS + BO_GUL + (size_t)l * 2 * WF, DLLM, DFF);
        transpose_split_kernel<<<dim3(DFF / 32, DLLM / 64), t32>>>(
            Wu + (size_t)l * WF, BS + BO_GUH + (size_t)l * 2 * WF + WF,
            BS + BO_GUL + (size_t)l * 2 * WF + WF, DLLM, DFF);
        transpose_split_kernel<<<dim3(DLLM / 32, DFF / 64), t32>>>(
            Wd + (size_t)l * WF, BS + BO_DWH + (size_t)l * WF,
            BS + BO_DWL + (size_t)l * WF, DFF, DLLM);
    }

    embed_gather_kernel<<<(B_ * SP * DLLM + 255) / 256, 256>>>(ids, etab, h);
    split_kernel<<<(int)((SZ_TV + 255) / 256), 256>>>(text, txh, txl, SZ_TV);
    split_kernel<<<(int)((SZ_TV + 255) / 256), 256>>>(vis, vxh, vxl, SZ_TV);
    launch_gemm(txh, txl, inwh, inwl, h, 512, DLLM, DMODEL, 2 | 4, inb, SP);
    launch_gemm(vxh, vxl, inwh, inwl, h, 512, DLLM, DMODEL, 2 | 4, inb, SP + ST);

    for (int l = 0; l < 2; l++) {
        rmsnorm_split_kernel<<<NTOK, 256>>>(h, ln1 + (size_t)l * DLLM, xnh, xnl);
        launch_gemm(xnh, xnl, BS + BO_QKVH + (size_t)l * 3 * W4,
                    BS + BO_QKVL + (size_t)l * 3 * W4,
                    qkv, NTOK, QKVS, DLLM, 0, nullptr, 0);
        rope_apply_kernel<<<(NTOK * NH * 64 + 255) / 256, 256>>>(qkv, cosb, sinb);
        attention_kernel<<<dim3(SEQ / 8, NH, B_), 256>>>(qkv, ath, atl);
        launch_gemm(ath, atl, BS + BO_OH + (size_t)l * W4, BS + BO_OL + (size_t)l * W4,
                    h, NTOK, DLLM, DLLM, 1, nullptr, 0);

        rmsnorm_split_kernel<<<NTOK, 256>>>(h, ln2 + (size_t)l * DLLM, xnh, xnl);
        launch_gemm(xnh, xnl, BS + BO_GUH + (size_t)l * 2 * WF,
                    BS + BO_GUL + (size_t)l * 2 * WF,
                    gu, NTOK, GUS, DLLM, 0, nullptr, 0);
        silu_mul_split_kernel<<<dim3(DFF / 256, NTOK), 256>>>(gu, gh, gl);
        launch_gemm(gh, gl, BS + BO_DWH + (size_t)l * WF, BS + BO_DWL + (size_t)l * WF,
                    h, NTOK, DLLM, DFF, 1, nullptr, 0);
    }

    rmsnorm_kernel<<<NTOK, 256>>>(h, fnw, xn);
    pool_kernel<<<(B_ * DLLM + 255) / 256, 256>>>(xn, pooled);
    head1_kernel<<<B_, 768>>>(pooled, o1W, o1b, y1);
    head2_kernel<<<B_, 256>>>(y1, o2W, o2b, out);
}

// round 12
// speedup vs baseline: 1.0498x; 1.0498x over previous
#include <cuda_runtime.h>
#include <cuda_bf16.h>
#include <math.h>
#include <stdint.h>

#define B_    8
#define SP    128
#define ST    64
#define SV    64
#define SEQ   256
#define DMODEL 768
#define DLLM  4096
#define NH    32
#define HD    128
#define DFF   11008
#define NTOK  (B_*SEQ)
#define QKVS  (3*DLLM)
#define GUS   (2*DFF)
#define EPS   1e-5f

// ---------------- fp32 scratch ----------------
#define SZ_TOKD ((size_t)NTOK*DLLM)
#define SZ_FF   ((size_t)NTOK*DFF)
#define OFF_H    ((size_t)0)
#define OFF_XN   (SZ_TOKD)
#define OFF_QKV  (2*SZ_TOKD)
#define OFF_GU   (5*SZ_TOKD)
#define OFF_COS  (OFF_GU + 2*SZ_FF)
#define OFF_SIN  (OFF_COS + (size_t)SEQ*64)
#define OFF_POOL (OFF_SIN + (size_t)SEQ*64)
#define OFF_Y1   (OFF_POOL + (size_t)B_*DLLM)
#define SCRATCH_TOTAL (OFF_Y1 + (size_t)B_*768)
__device__ float g_scratch[SCRATCH_TOTAL];

// ---------------- bf16 scratch ----------------
#define W4 ((size_t)DLLM*DLLM)
#define WF ((size_t)DLLM*DFF)
#define SZ_TV  ((size_t)512*DMODEL)
#define SZ_INW ((size_t)DMODEL*DLLM)
#define BO_XNH  ((size_t)0)
#define BO_XNL  (BO_XNH + SZ_TOKD)
#define BO_ATH  (BO_XNL + SZ_TOKD)
#define BO_ATL  (BO_ATH + SZ_TOKD)
#define BO_GH   (BO_ATL + SZ_TOKD)
#define BO_GL   (BO_GH + SZ_FF)
#define BO_TXH  (BO_GL + SZ_FF)
#define BO_TXL  (BO_TXH + SZ_TV)
#define BO_VXH  (BO_TXL + SZ_TV)
#define BO_VXL  (BO_VXH + SZ_TV)
#define BO_INWH (BO_VXL + SZ_TV)
#define BO_INWL (BO_INWH + SZ_INW)
#define BO_QKVH (BO_INWL + SZ_INW)
#define BO_QKVL (BO_QKVH + 6*W4)
#define BO_OH   (BO_QKVL + 6*W4)
#define BO_OL   (BO_OH + 2*W4)
#define BO_GUH  (BO_OL + 2*W4)
#define BO_GUL  (BO_GUH + 4*WF)
#define BO_DWH  (BO_GUL + 4*WF)
#define BO_DWL  (BO_DWH + 2*WF)
#define BF_TOTAL (BO_DWL + 2*WF)
__device__ __align__(256) __nv_bfloat16 g_bf[BF_TOTAL];

// ---------------- helpers ----------------
__device__ __forceinline__ uint32_t smem_u32(const void* p) {
    uint32_t a;
    asm("{ .reg .u64 t; cvta.to.shared.u64 t, %1; cvt.u32.u64 %0, t; }" : "=r"(a) : "l"(p));
    return a;
}
__device__ __forceinline__ void cp16(uint32_t d, const void* s) {
    asm volatile("cp.async.cg.shared.global [%0], [%1], 16;" :: "r"(d), "l"(s));
}
__device__ __forceinline__ void split_bf(float x, __nv_bfloat16& h, __nv_bfloat16& l) {
    h = __float2bfloat16_rn(x);
    l = __float2bfloat16_rn(x - __bfloat162float(h));
}
__device__ __forceinline__ void mma_bf16(float* c,
    uint32_t a0, uint32_t a1, uint32_t a2, uint32_t a3, uint32_t b0, uint32_t b1) {
    asm volatile(
        "mma.sync.aligned.m16n8k16.row.col.f32.bf16.bf16.f32 "
        "{%0,%1,%2,%3}, {%4,%5,%6,%7}, {%8,%9}, {%0,%1,%2,%3};"
        : "+f"(c[0]), "+f"(c[1]), "+f"(c[2]), "+f"(c[3])
        : "r"(a0), "r"(a1), "r"(a2), "r"(a3), "r"(b0), "r"(b1));
}
__device__ __forceinline__ void ldm_x4(uint32_t& r0, uint32_t& r1,
                                       uint32_t& r2, uint32_t& r3, uint32_t a) {
    asm volatile("ldmatrix.sync.aligned.m8n8.x4.shared.b16 {%0,%1,%2,%3}, [%4];"
        : "=r"(r0), "=r"(r1), "=r"(r2), "=r"(r3) : "r"(a));
}

// ---------------------------------------------------------------------------
// bf16-split GEMM via mma.sync + ldmatrix. BM=128, BN=64, BK=32.
// C[M,N] = A[M,K] @ W[K,N]; A=Ah+Al [M,K] bf16; W^T=Bh+Bl [N,K] bf16.
// 3 passes AhBh + AhBl + AlBh, fp32 accum, 3-stage cp.async, 2 CTAs/SM.
// flags: 1 accumulate, 2 bias, 4 row remap. M%128==0, N%64==0, K%32==0.
// ---------------------------------------------------------------------------
#define TPITCH 40
#define O_AH 0
#define O_AL (128*TPITCH)
#define O_BH (256*TPITCH)
#define O_BL (320*TPITCH)
#define STAGE_E (384*TPITCH)          // 15360 elements
#define GSMEM_BYTES (3*STAGE_E*2)     // 92160 B

__global__ __launch_bounds__(256, 2) void gemm_tc(
    const __nv_bfloat16* __restrict__ Ah, const __nv_bfloat16* __restrict__ Al,
    const __nv_bfloat16* __restrict__ Bh, const __nv_bfloat16* __restrict__ Bl,
    float* __restrict__ C, int M, int N, int K,
    int flags, const float* __restrict__ bias, int map_base)
{
    extern __shared__ __nv_bfloat16 sm[];
    const int tid = threadIdx.x;
    const int wid = tid >> 5, lane = tid & 31;
    const int wm = wid & 3, wn = wid >> 2;          // 4 m-warps x 2 n-warps
    const int m0 = blockIdx.y * 128, n0 = blockIdx.x * 64;
    const int gr = lane >> 2, qc = lane & 3;
    const uint32_t smbase = smem_u32(sm);

    const uint32_t aoff = (uint32_t)(((wm * 32 + (lane & 15)) * TPITCH + ((lane >> 4) << 3)) * 2);
    const uint32_t boff = (uint32_t)(((wn * 32 + ((lane >> 4) << 3) + (lane & 7)) * TPITCH
                                      + (((lane >> 3) & 1) << 3)) * 2);

    // Loader: 1536 16B chunks / stage, 6 per thread
    const __nv_bfloat16* gp[6];
    uint32_t soff[6];
#pragma unroll
    for (int i = 0; i < 6; i++) {
        int c = tid + i * 256;
        const __nv_bfloat16* base; int row, tbase;
        if (c < 512)       { base = Ah; row = c >> 2;          tbase = O_AH; }
        else if (c < 1024) { base = Al; row = (c - 512) >> 2;  tbase = O_AL; }
        else if (c < 1280) { base = Bh; row = (c - 1024) >> 2; tbase = O_BH; }
        else               { base = Bl; row = (c - 1280) >> 2; tbase = O_BL; }
        int sub = c & 3;
        int grow = ((c < 1024) ? m0 : n0) + row;
        gp[i] = base + (size_t)grow * K + sub * 8;
        soff[i] = (uint32_t)((tbase + row * TPITCH + sub * 8) * 2);
    }

#define LOAD_STAGE(s_) do { \
    uint32_t sb_ = smbase + (uint32_t)(((s_) % 3) * STAGE_E * 2); \
    _Pragma("unroll") \
    for (int i_ = 0; i_ < 6; i_++) \
        cp16(sb_ + soff[i_], gp[i_] + (size_t)(s_) * 32); \
    asm volatile("cp.async.commit_group;" ::: "memory"); \
} while (0)

    const int S = K / 32;
    LOAD_STAGE(0);
    LOAD_STAGE(1);

    float acc[2][4][4];
#pragma unroll
    for (int t = 0; t < 2; t++)
#pragma unroll
        for (int n = 0; n < 4; n++)
#pragma unroll
            for (int e = 0; e < 4; e++) acc[t][n][e] = 0.f;

    for (int s = 0; s < S; s++) {
        asm volatile("cp.async.wait_group 1;" ::: "memory");
        __syncthreads();
        if (s + 2 < S) { LOAD_STAGE(s + 2); }
        else { asm volatile("cp.async.commit_group;" ::: "memory"); }

        const uint32_t stg = smbase + (uint32_t)((s % 3) * STAGE_E * 2);

#pragma unroll
        for (int kk = 0; kk < 32; kk += 16) {
            uint32_t ah[2][4], al[2][4], bh[4][2], bl[4][2];
#pragma unroll
            for (int t = 0; t < 2; t++) {
                uint32_t off = aoff + (uint32_t)((t * 16 * TPITCH + kk) * 2);
                ldm_x4(ah[t][0], ah[t][1], ah[t][2], ah[t][3], stg + O_AH * 2 + off);
                ldm_x4(al[t][0], al[t][1], al[t][2], al[t][3], stg + O_AL * 2 + off);
            }
#pragma unroll
            for (int j = 0; j < 2; j++) {
                uint32_t off = boff + (uint32_t)((j * 16 * TPITCH + kk) * 2);
                ldm_x4(bh[2*j][0], bh[2*j][1], bh[2*j+1][0], bh[2*j+1][1], stg + O_BH * 2 + off);
                ldm_x4(bl[2*j][0], bl[2*j][1], bl[2*j+1][0], bl[2*j+1][1], stg + O_BL * 2 + off);
            }
#pragma unroll
            for (int t = 0; t < 2; t++)
#pragma unroll
                for (int n = 0; n < 4; n++) {
                    mma_bf16(acc[t][n], ah[t][0], ah[t][1], ah[t][2], ah[t][3],
                             bh[n][0], bh[n][1]);
                    mma_bf16(acc[t][n], ah[t][0], ah[t][1], ah[t][2], ah[t][3],
                             bl[n][0], bl[n][1]);
                    mma_bf16(acc[t][n], al[t][0], al[t][1], al[t][2], al[t][3],
                             bh[n][0], bh[n][1]);
                }
        }
    }

    // Epilogue
#pragma unroll
    for (int t = 0; t < 2; t++) {
#pragma unroll
        for (int half = 0; half < 2; half++) {
            int grow = m0 + wm * 32 + t * 16 + gr + half * 8;
            int orow = (flags & 4) ? ((grow >> 6) * SEQ + map_base + (grow & 63)) : grow;
            float* crow = C + (size_t)orow * N;
#pragma unroll
            for (int n = 0; n < 4; n++) {
                int col = n0 + wn * 32 + n * 8 + qc * 2;
                float2 v;
                v.x = acc[t][n][half * 2 + 0];
                v.y = acc[t][n][half * 2 + 1];
                if (flags & 2) {
                    float2 b2 = *reinterpret_cast<const float2*>(bias + col);
                    v.x += b2.x; v.y += b2.y;
                }
                if (flags & 1) {
                    float2 o = *reinterpret_cast<const float2*>(crow + col);
                    v.x += o.x; v.y += o.y;
                }
                *reinterpret_cast<float2*>(crow + col) = v;
            }
        }
    }
#undef LOAD_STAGE
}

// ---------------- transpose + split: src[K,N] fp32 -> [N,K] bf16 hi/lo ------
// 64(k) x 32(n) tile; __nv_bfloat162 writes give 128B store segments.
// grid (N/32, K/64), block (32,8).
__global__ void transpose_split_kernel(
    const float* __restrict__ src,
    __nv_bfloat16* __restrict__ dhi, __nv_bfloat16* __restrict__ dlo,
    int K, int N)
{
    __shared__ float tile[64][33];
    const int n0 = blockIdx.x * 32, k0 = blockIdx.y * 64;
    const int tx = threadIdx.x, ty = threadIdx.y;
#pragma unroll
    for (int i = 0; i < 64; i += 8)
        tile[ty + i][tx] = src[(size_t)(k0 + ty + i) * N + n0 + tx];
    __syncthreads();
#pragma unroll
    for (int j = 0; j < 32; j += 8) {
        int nrow = ty + j;
        float v0 = tile[2 * tx][nrow];
        float v1 = tile[2 * tx + 1][nrow];
        __nv_bfloat16 h0, l0, h1, l1;
        split_bf(v0, h0, l0);
        split_bf(v1, h1, l1);
        size_t idx = (size_t)(n0 + nrow) * K + k0 + 2 * tx;
        *reinterpret_cast<__nv_bfloat162*>(dhi + idx) = __nv_bfloat162(h0, h1);
        *reinterpret_cast<__nv_bfloat162*>(dlo + idx) = __nv_bfloat162(l0, l1);
    }
}

__global__ void split_kernel(const float* __restrict__ src,
                             __nv_bfloat16* __restrict__ hi,
                             __nv_bfloat16* __restrict__ lo, size_t n)
{
    size_t idx = (size_t)blockIdx.x * blockDim.x + threadIdx.x;
    if (idx >= n) return;
    __nv_bfloat16 h, l;
    split_bf(src[idx], h, l);
    hi[idx] = h; lo[idx] = l;
}

__global__ void rope_table_kernel(float* __restrict__ cosb, float* __restrict__ sinb)
{
    int idx = blockIdx.x * blockDim.x + threadIdx.x;
    if (idx >= SEQ * 64) return;
    int s = idx >> 6, i = idx & 63;
    double inv = exp(-((double)(2 * i) / 128.0) * log(10000.0));
    double ang = (double)s * inv;
    cosb[idx] = (float)cos(ang);
    sinb[idx] = (float)sin(ang);
}

__global__ void embed_gather_kernel(const int* __restrict__ ids,
                                    const float* __restrict__ table,
                                    float* __restrict__ h)
{
    int idx = blockIdx.x * blockDim.x + threadIdx.x;
    if (idx >= B_ * SP * DLLM) return;
    int d = idx & (DLLM - 1);
    int r = (idx >> 12) & (SP - 1);
    int b = idx >> 19;
    int id = ids[b * SP + r];
    h[((size_t)(b * SEQ + r)) * DLLM + d] = table[(size_t)id * DLLM + d];
}

__global__ __launch_bounds__(256) void rmsnorm_kernel(
    const float* __restrict__ x, const float* __restrict__ w, float* __restrict__ out)
{
    int t = blockIdx.x;
    const float4* xr = reinterpret_cast<const float4*>(x + (size_t)t * DLLM);
    float4 vals[4];
    float s = 0.f;
#pragma unroll
    for (int j = 0; j < 4; j++) {
        float4 v = xr[threadIdx.x + j * 256];
        vals[j] = v;
        s += v.x * v.x + v.y * v.y + v.z * v.z + v.w * v.w;
    }
#pragma unroll
    for (int off = 16; off > 0; off >>= 1) s += __shfl_xor_sync(0xffffffffu, s, off);
    __shared__ float red[8];
    __shared__ float sscale;
    if ((threadIdx.x & 31) == 0) red[threadIdx.x >> 5] = s;
    __syncthreads();
    if (threadIdx.x == 0) {
        float r = 0.f;
#pragma unroll
        for (int i = 0; i < 8; i++) r += red[i];
        sscale = rsqrtf(r * (1.0f / DLLM) + EPS);
    }
    __syncthreads();
    float sc = sscale;
    const float4* w4 = reinterpret_cast<const float4*>(w);
    float4* o4 = reinterpret_cast<float4*>(out + (size_t)t * DLLM);
#pragma unroll
    for (int j = 0; j < 4; j++) {
        float4 v = vals[j];
        float4 wv = w4[threadIdx.x + j * 256];
        o4[threadIdx.x + j * 256] = make_float4(
            v.x * sc * wv.x, v.y * sc * wv.y, v.z * sc * wv.z, v.w * sc * wv.w);
    }
}

__global__ __launch_bounds__(256) void rmsnorm_split_kernel(
    const float* __restrict__ x, const float* __restrict__ w,
    __nv_bfloat16* __restrict__ ohi, __nv_bfloat16* __restrict__ olo)
{
    int t = blockIdx.x;
    const float4* xr = reinterpret_cast<const float4*>(x + (size_t)t * DLLM);
    float4 vals[4];
    float s = 0.f;
#pragma unroll
    for (int j = 0; j < 4; j++) {
        float4 v = xr[threadIdx.x + j * 256];
        vals[j] = v;
        s += v.x * v.x + v.y * v.y + v.z * v.z + v.w * v.w;
    }
#pragma unroll
    for (int off = 16; off > 0; off >>= 1) s += __shfl_xor_sync(0xffffffffu, s, off);
    __shared__ float red[8];
    __shared__ float sscale;
    if ((threadIdx.x & 31) == 0) red[threadIdx.x >> 5] = s;
    __syncthreads();
    if (threadIdx.x == 0) {
        float r = 0.f;
#pragma unroll
        for (int i = 0; i < 8; i++) r += red[i];
        sscale = rsqrtf(r * (1.0f / DLLM) + EPS);
    }
    __syncthreads();
    float sc = sscale;
    const float4* w4 = reinterpret_cast<const float4*>(w);
    size_t base = (size_t)t * DLLM;
#pragma unroll
    for (int j = 0; j < 4; j++) {
        float4 v = vals[j];
        float4 wv = w4[threadIdx.x + j * 256];
        float rr[4] = { v.x * sc * wv.x, v.y * sc * wv.y, v.z * sc * wv.z, v.w * sc * wv.w };
        size_t o = base + ((size_t)threadIdx.x + j * 256) * 4;
#pragma unroll
        for (int e = 0; e < 4; e++) {
            __nv_bfloat16 h, l;
            split_bf(rr[e], h, l);
            ohi[o + e] = h; olo[o + e] = l;
        }
    }
}

__global__ void rope_apply_kernel(float* __restrict__ qkv,
                                  const float* __restrict__ cosb,
                                  const float* __restrict__ sinb)
{
    int idx = blockIdx.x * blockDim.x + threadIdx.x;
    if (idx >= NTOK * NH * 64) return;
    int i = idx & 63;
    int h = (idx >> 6) & (NH - 1);
    int t = idx >> 11;
    int s = t & (SEQ - 1);
    float c = cosb[s * 64 + i];
    float sn = sinb[s * 64 + i];
    size_t base = (size_t)t * QKVS + h * HD + i;
    float x1 = qkv[base], x2 = qkv[base + 64];
    qkv[base]      = x1 * c - x2 * sn;
    qkv[base + 64] = x2 * c + x1 * sn;
    size_t kb = base + DLLM;
    x1 = qkv[kb]; x2 = qkv[kb + 64];
    qkv[kb]      = x1 * c - x2 * sn;
    qkv[kb + 64] = x2 * c + x1 * sn;
}

__global__ __launch_bounds__(256) void attention_kernel(
    const float* __restrict__ qkv,
    __nv_bfloat16* __restrict__ ohi, __nv_bfloat16* __restrict__ olo)
{
    __shared__ float sc[8][SEQ];
    const int b = blockIdx.z, hh = blockIdx.y;
    const int w = threadIdx.x >> 5, lane = threadIdx.x & 31;
    const int qi = blockIdx.x * 8 + w;
    const float scale = 0.088388347648318447f;

    const float* qrow = qkv + (size_t)(b * SEQ + qi) * QKVS + hh * HD;
    float4 qv = reinterpret_cast<const float4*>(qrow)[lane];

    const float* kbase = qkv + (size_t)b * SEQ * QKVS + DLLM + hh * HD;
    for (int kk = 0; kk <= qi; kk++) {
        float4 kv = reinterpret_cast<const float4*>(kbase + (size_t)kk * QKVS)[lane];
        float d = qv.x * kv.x + qv.y * kv.y + qv.z * kv.z + qv.w * kv.w;
#pragma unroll
        for (int off = 16; off > 0; off >>= 1) d += __shfl_xor_sync(0xffffffffu, d, off);
        if (lane == 0) sc[w][kk] = d * scale;
    }
    __syncwarp();

    float m = -1e30f;
    for (int kk = lane; kk <= qi; kk += 32) m = fmaxf(m, sc[w][kk]);
#pragma unroll
    for (int off = 16; off > 0; off >>= 1) m = fmaxf(m, __shfl_xor_sync(0xffffffffu, m, off));

    float ssum = 0.f;
    for (int kk = lane; kk <= qi; kk += 32) {
        float p = expf(sc[w][kk] - m);
        sc[w][kk] = p;
        ssum += p;
    }
#pragma unroll
    for (int off = 16; off > 0; off >>= 1) ssum += __shfl_xor_sync(0xffffffffu, ssum, off);
    __syncwarp();
    float inv = 1.0f / ssum;

    const float* vbase = qkv + (size_t)b * SEQ * QKVS + 2 * DLLM + hh * HD;
    float4 acc = make_float4(0.f, 0.f, 0.f, 0.f);
    for (int kk = 0; kk <= qi; kk++) {
        float p = sc[w][kk];
        float4 vv = reinterpret_cast<const float4*>(vbase + (size_t)kk * QKVS)[lane];
        acc.x += p * vv.x; acc.y += p * vv.y;
        acc.z += p * vv.z; acc.w += p * vv.w;
    }
    size_t o = (size_t)(b * SEQ + qi) * DLLM + hh * HD + lane * 4;
    float r[4] = { acc.x * inv, acc.y * inv, acc.z * inv, acc.w * inv };
#pragma unroll
    for (int e = 0; e < 4; e++) {
        __nv_bfloat16 h, l;
        split_bf(r[e], h, l);
        ohi[o + e] = h; olo[o + e] = l;
    }
}

__global__ void silu_mul_split_kernel(const float* __restrict__ gu,
                                      __nv_bfloat16* __restrict__ ohi,
                                      __nv_bfloat16* __restrict__ olo)
{
    int j = blockIdx.x * 256 + threadIdx.x;
    int t = blockIdx.y;
    const float* row = gu + (size_t)t * GUS;
    float x = row[j];
    float r = (x / (1.0f + expf(-x))) * row[DFF + j];
    __nv_bfloat16 h, l;
    split_bf(r, h, l);
    size_t o = (size_t)t * DFF + j;
    ohi[o] = h; olo[o] = l;
}

__global__ void pool_kernel(const float* __restrict__ xn, float* __restrict__ pooled)
{
    int idx = blockIdx.x * blockDim.x + threadIdx.x;
    if (idx >= B_ * DLLM) return;
    int b = idx >> 12, d = idx & (DLLM - 1);
    float s = 0.f;
    for (int t = 0; t < SEQ; t++)
        s += xn[(size_t)(b * SEQ + t) * DLLM + d];
    pooled[idx] = s * (1.0f / SEQ);
}

__global__ void head1_kernel(const float* __restrict__ pooled,
                             const float* __restrict__ W,
                             const float* __restrict__ bias,
                             float* __restrict__ y1)
{
    int b = blockIdx.x, j = threadIdx.x;
    const float* p = pooled + (size_t)b * DLLM;
    float s = bias[j];
    for (int i = 0; i < DLLM; i++) s += p[i] * W[(size_t)i * 768 + j];
    y1[b * 768 + j] = s;
}

__global__ void head2_kernel(const float* __restrict__ y1,
                             const float* __restrict__ W,
                             const float* __restrict__ bias,
                             float* __restrict__ out)
{
    int b = blockIdx.x;
    float s = 0.f;
    for (int j = threadIdx.x; j < 768; j += 256) s += y1[b * 768 + j] * W[j];
#pragma unroll
    for (int off = 16; off > 0; off >>= 1) s += __shfl_xor_sync(0xffffffffu, s, off);
    __shared__ float red[8];
    if ((threadIdx.x & 31) == 0) red[threadIdx.x >> 5] = s;
    __syncthreads();
    if (threadIdx.x == 0) {
        float r = 0.f;
#pragma unroll
        for (int i = 0; i < 8; i++) r += red[i];
        out[b] = r + bias[0];
    }
}

// ---------------------------------------------------------------------------
extern "C" void kernel_launch(void* const* d_in, const int* in_sizes, int n_in,
                              void* d_out, int out_size)
{
    const float* text  = (const float*)d_in[0];
    const float* vis   = (const float*)d_in[1];
    const int*   ids   = (const int*)  d_in[2];
    const float* inW   = (const float*)d_in[3];
    const float* inb   = (const float*)d_in[4];
    const float* etab  = (const float*)d_in[5];
    const float* Wq    = (const float*)d_in[6];
    const float* Wk    = (const float*)d_in[7];
    const float* Wv    = (const float*)d_in[8];
    const float* Wo    = (const float*)d_in[9];
    const float* ln1   = (const float*)d_in[10];
    const float* ln2   = (const float*)d_in[11];
    const float* Wg    = (const float*)d_in[12];
    const float* Wu    = (const float*)d_in[13];
    const float* Wd    = (const float*)d_in[14];
    const float* fnw   = (const float*)d_in[15];
    const float* o1W   = (const float*)d_in[16];
    const float* o1b   = (const float*)d_in[17];
    const float* o2W   = (const float*)d_in[18];
    const float* o2b   = (const float*)d_in[19];
    float* out = (float*)d_out;

    cudaFuncSetAttribute(gemm_tc, cudaFuncAttributeMaxDynamicSharedMemorySize,
                         GSMEM_BYTES);

    float* S = nullptr;
    cudaGetSymbolAddress((void**)&S, g_scratch);
    __nv_bfloat16* BS = nullptr;
    cudaGetSymbolAddress((void**)&BS, g_bf);

    float* h    = S + OFF_H;
    float* xn   = S + OFF_XN;
    float* qkv  = S + OFF_QKV;
    float* gu   = S + OFF_GU;
    float* cosb = S + OFF_COS;
    float* sinb = S + OFF_SIN;
    float* pooled = S + OFF_POOL;
    float* y1   = S + OFF_Y1;

    __nv_bfloat16 *xnh = BS + BO_XNH, *xnl = BS + BO_XNL;
    __nv_bfloat16 *ath = BS + BO_ATH, *atl = BS + BO_ATL;
    __nv_bfloat16 *gh  = BS + BO_GH,  *gl  = BS + BO_GL;
    __nv_bfloat16 *txh = BS + BO_TXH, *txl = BS + BO_TXL;
    __nv_bfloat16 *vxh = BS + BO_VXH, *vxl = BS + BO_VXL;
    __nv_bfloat16 *inwh = BS + BO_INWH, *inwl = BS + BO_INWL;

    dim3 t32(32, 8);

    rope_table_kernel<<<(SEQ * 64 + 255) / 256, 256>>>(cosb, sinb);

    transpose_split_kernel<<<dim3(DLLM / 32, DMODEL / 64), t32>>>(inW, inwh, inwl, DMODEL, DLLM);
    for (int l = 0; l < 2; l++) {
        transpose_split_kernel<<<dim3(DLLM / 32, DLLM / 64), t32>>>(
            Wq + (size_t)l * W4, BS + BO_QKVH + (size_t)l * 3 * W4,
            BS + BO_QKVL + (size_t)l * 3 * W4, DLLM, DLLM);
        transpose_split_kernel<<<dim3(DLLM / 32, DLLM / 64), t32>>>(
            Wk + (size_t)l * W4, BS + BO_QKVH + (size_t)l * 3 * W4 + W4,
            BS + BO_QKVL + (size_t)l * 3 * W4 + W4, DLLM, DLLM);
        transpose_split_kernel<<<dim3(DLLM / 32, DLLM / 64), t32>>>(
            Wv + (size_t)l * W4, BS + BO_QKVH + (size_t)l * 3 * W4 + 2 * W4,
            BS + BO_QKVL + (size_t)l * 3 * W4 + 2 * W4, DLLM, DLLM);
        transpose_split_kernel<<<dim3(DLLM / 32, DLLM / 64), t32>>>(
            Wo + (size_t)l * W4, BS + BO_OH + (size_t)l * W4,
            BS + BO_OL + (size_t)l * W4, DLLM, DLLM);
        transpose_split_kernel<<<dim3(DFF / 32, DLLM / 64), t32>>>(
            Wg + (size_t)l * WF, BS + BO_GUH + (size_t)l * 2 * WF,
            BS + BO_GUL + (size_t)l * 2 * WF, DLLM, DFF);
        transpose_split_kernel<<<dim3(DFF / 32, DLLM / 64), t32>>>(
            Wu + (size_t)l * WF, BS + BO_GUH + (size_t)l * 2 * WF + WF,
            BS + BO_GUL + (size_t)l * 2 * WF + WF, DLLM, DFF);
        transpose_split_kernel<<<dim3(DLLM / 32, DFF / 64), t32>>>(
            Wd + (size_t)l * WF, BS + BO_DWH + (size_t)l * WF,
            BS + BO_DWL + (size_t)l * WF, DFF, DLLM);
    }

    embed_gather_kernel<<<(B_ * SP * DLLM + 255) / 256, 256>>>(ids, etab, h);
    split_kernel<<<(int)((SZ_TV + 255) / 256), 256>>>(text, txh, txl, SZ_TV);
    split_kernel<<<(int)((SZ_TV + 255) / 256), 256>>>(vis, vxh, vxl, SZ_TV);
    gemm_tc<<<dim3(DLLM / 64, 512 / 128), 256, GSMEM_BYTES>>>(
        txh, txl, inwh, inwl, h, 512, DLLM, DMODEL, 2 | 4, inb, SP);
    gemm_tc<<<dim3(DLLM / 64, 512 / 128), 256, GSMEM_BYTES>>>(
        vxh, vxl, inwh, inwl, h, 512, DLLM, DMODEL, 2 | 4, inb, SP + ST);

    for (int l = 0; l < 2; l++) {
        rmsnorm_split_kernel<<<NTOK, 256>>>(h, ln1 + (size_t)l * DLLM, xnh, xnl);
        gemm_tc<<<dim3(QKVS / 64, NTOK / 128), 256, GSMEM_BYTES>>>(
            xnh, xnl, BS + BO_QKVH + (size_t)l * 3 * W4, BS + BO_QKVL + (size_t)l * 3 * W4,
            qkv, NTOK, QKVS, DLLM, 0, nullptr, 0);
        rope_apply_kernel<<<(NTOK * NH * 64 + 255) / 256, 256>>>(qkv, cosb, sinb);
        attention_kernel<<<dim3(SEQ / 8, NH, B_), 256>>>(qkv, ath, atl);
        gemm_tc<<<dim3(DLLM / 64, NTOK / 128), 256, GSMEM_BYTES>>>(
            ath, atl, BS + BO_OH + (size_t)l * W4, BS + BO_OL + (size_t)l * W4,
            h, NTOK, DLLM, DLLM, 1, nullptr, 0);

        rmsnorm_split_kernel<<<NTOK, 256>>>(h, ln2 + (size_t)l * DLLM, xnh, xnl);
        gemm_tc<<<dim3(GUS / 64, NTOK / 128), 256, GSMEM_BYTES>>>(
            xnh, xnl, BS + BO_GUH + (size_t)l * 2 * WF, BS + BO_GUL + (size_t)l * 2 * WF,
            gu, NTOK, GUS, DLLM, 0, nullptr, 0);
        silu_mul_split_kernel<<<dim3(DFF / 256, NTOK), 256>>>(gu, gh, gl);
        gemm_tc<<<dim3(DLLM / 64, NTOK / 128), 256, GSMEM_BYTES>>>(
            gh, gl, BS + BO_DWH + (size_t)l * WF, BS + BO_DWL + (size_t)l * WF,
            h, NTOK, DLLM, DFF, 1, nullptr, 0);
    }

    rmsnorm_kernel<<<NTOK, 256>>>(h, fnw, xn);
    pool_kernel<<<(B_ * DLLM + 255) / 256, 256>>>(xn, pooled);
    head1_kernel<<<B_, 768>>>(pooled, o1W, o1b, y1);
    head2_kernel<<<B_, 256>>>(y1, o2W, o2b, out);
}

// round 13
// speedup vs baseline: 1.0777x; 1.0266x over previous
#include <cuda_runtime.h>
#include <cuda_bf16.h>
#include <math.h>
#include <stdint.h>

#define B_    8
#define SP    128
#define ST    64
#define SV    64
#define SEQ   256
#define DMODEL 768
#define DLLM  4096
#define NH    32
#define HD    128
#define DFF   11008
#define NTOK  (B_*SEQ)
#define QKVS  (3*DLLM)
#define GUS   (2*DFF)
#define EPS   1e-5f

// ---------------- fp32 scratch ----------------
#define SZ_TOKD ((size_t)NTOK*DLLM)
#define SZ_FF   ((size_t)NTOK*DFF)
#define OFF_H    ((size_t)0)
#define OFF_XN   (SZ_TOKD)
#define OFF_QKV  (2*SZ_TOKD)
#define OFF_GU   (5*SZ_TOKD)
#define OFF_COS  (OFF_GU + 2*SZ_FF)
#define OFF_SIN  (OFF_COS + (size_t)SEQ*64)
#define OFF_POOL (OFF_SIN + (size_t)SEQ*64)
#define OFF_Y1   (OFF_POOL + (size_t)B_*DLLM)
#define SCRATCH_TOTAL (OFF_Y1 + (size_t)B_*768)
__device__ float g_scratch[SCRATCH_TOTAL];

// ---------------- bf16 scratch (weights now [K,N] layout) ----------------
#define W4 ((size_t)DLLM*DLLM)
#define WF ((size_t)DLLM*DFF)
#define SZ_TV  ((size_t)512*DMODEL)
#define SZ_INW ((size_t)DMODEL*DLLM)
#define BO_XNH  ((size_t)0)
#define BO_XNL  (BO_XNH + SZ_TOKD)
#define BO_ATH  (BO_XNL + SZ_TOKD)
#define BO_ATL  (BO_ATH + SZ_TOKD)
#define BO_GH   (BO_ATL + SZ_TOKD)
#define BO_GL   (BO_GH + SZ_FF)
#define BO_TXH  (BO_GL + SZ_FF)
#define BO_TXL  (BO_TXH + SZ_TV)
#define BO_VXH  (BO_TXL + SZ_TV)
#define BO_VXL  (BO_VXH + SZ_TV)
#define BO_INWH (BO_VXL + SZ_TV)
#define BO_INWL (BO_INWH + SZ_INW)
#define BO_QKVH (BO_INWL + SZ_INW)          // per layer: [4096, 12288]
#define BO_QKVL (BO_QKVH + 6*W4)
#define BO_OH   (BO_QKVL + 6*W4)            // per layer: [4096, 4096]
#define BO_OL   (BO_OH + 2*W4)
#define BO_GUH  (BO_OL + 2*W4)              // per layer: [4096, 22016]
#define BO_GUL  (BO_GUH + 4*WF)
#define BO_DWH  (BO_GUL + 4*WF)             // per layer: [11008, 4096]
#define BO_DWL  (BO_DWH + 2*WF)
#define BF_TOTAL (BO_DWL + 2*WF)
__device__ __align__(256) __nv_bfloat16 g_bf[BF_TOTAL];

// ---------------- helpers ----------------
__device__ __forceinline__ uint32_t smem_u32(const void* p) {
    uint32_t a;
    asm("{ .reg .u64 t; cvta.to.shared.u64 t, %1; cvt.u32.u64 %0, t; }" : "=r"(a) : "l"(p));
    return a;
}
__device__ __forceinline__ void cp16(uint32_t d, const void* s) {
    asm volatile("cp.async.cg.shared.global [%0], [%1], 16;" :: "r"(d), "l"(s));
}
__device__ __forceinline__ void split_bf(float x, __nv_bfloat16& h, __nv_bfloat16& l) {
    h = __float2bfloat16_rn(x);
    l = __float2bfloat16_rn(x - __bfloat162float(h));
}
__device__ __forceinline__ void mma_bf16(float* c,
    uint32_t a0, uint32_t a1, uint32_t a2, uint32_t a3, uint32_t b0, uint32_t b1) {
    asm volatile(
        "mma.sync.aligned.m16n8k16.row.col.f32.bf16.bf16.f32 "
        "{%0,%1,%2,%3}, {%4,%5,%6,%7}, {%8,%9}, {%0,%1,%2,%3};"
        : "+f"(c[0]), "+f"(c[1]), "+f"(c[2]), "+f"(c[3])
        : "r"(a0), "r"(a1), "r"(a2), "r"(a3), "r"(b0), "r"(b1));
}
__device__ __forceinline__ void ldm_x4(uint32_t& r0, uint32_t& r1,
                                       uint32_t& r2, uint32_t& r3, uint32_t a) {
    asm volatile("ldmatrix.sync.aligned.m8n8.x4.shared.b16 {%0,%1,%2,%3}, [%4];"
        : "=r"(r0), "=r"(r1), "=r"(r2), "=r"(r3) : "r"(a));
}
__device__ __forceinline__ void ldm_x4t(uint32_t& r0, uint32_t& r1,
                                        uint32_t& r2, uint32_t& r3, uint32_t a) {
    asm volatile("ldmatrix.sync.aligned.m8n8.x4.trans.shared.b16 {%0,%1,%2,%3}, [%4];"
        : "=r"(r0), "=r"(r1), "=r"(r2), "=r"(r3) : "r"(a));
}

// ---------------------------------------------------------------------------
// bf16-split GEMM via mma.sync + ldmatrix. BM=128, BN=64, BK=32.
// C[M,N] = A[M,K] @ W[K,N]; A=Ah+Al [M,K] bf16; W=Bh+Bl [K,N] bf16 (NO transpose;
// B fragments via ldmatrix.trans). 3 passes AhBh + AhBl + AlBh, fp32 accum,
// 3-stage cp.async, 2 CTAs/SM.
// flags: 1 accumulate, 2 bias, 4 row remap. M%128==0, N%64==0, K%32==0.
// ---------------------------------------------------------------------------
#define TPITCH 40
#define BPITCH 72
#define O_AH 0
#define O_AL (128*TPITCH)                 // 5120
#define O_BH (256*TPITCH)                 // 10240
#define O_BL (O_BH + 32*BPITCH)           // 12544
#define STAGE_E (O_BH + 64*BPITCH)        // 14848 elements
#define GSMEM_BYTES (3*STAGE_E*2)         // 89088 B

__global__ __launch_bounds__(256, 2) void gemm_tc(
    const __nv_bfloat16* __restrict__ Ah, const __nv_bfloat16* __restrict__ Al,
    const __nv_bfloat16* __restrict__ Bh, const __nv_bfloat16* __restrict__ Bl,
    float* __restrict__ C, int M, int N, int K,
    int flags, const float* __restrict__ bias, int map_base)
{
    extern __shared__ __nv_bfloat16 sm[];
    const int tid = threadIdx.x;
    const int wid = tid >> 5, lane = tid & 31;
    const int wm = wid & 3, wn = wid >> 2;          // 4 m-warps x 2 n-warps
    const int m0 = blockIdx.y * 128, n0 = blockIdx.x * 64;
    const int gr = lane >> 2, qc = lane & 3;
    const uint32_t smbase = smem_u32(sm);

    // A ldmatrix per-lane offset (within tile, elements*2 = bytes)
    const uint32_t aoff = (uint32_t)(((wm * 32 + (lane & 15)) * TPITCH + ((lane >> 4) << 3)) * 2);
    // B trans ldmatrix per-lane components: k-row part + n-col part
    const int bko = ((lane >> 3) & 1) * 8 + (lane & 7);      // k row within 16-slab
    const int bno = wn * 32 + ((lane >> 4) << 3);            // n col base

    // Loader: 1536 16B chunks / stage, 6 per thread.
    // A: 1024 chunks ([M,K], advance 32 elems/stage).
    // B: 512 chunks ([K,N], advance 32*N elems/stage).
    const __nv_bfloat16* gp[6];
    size_t adv[6];
    uint32_t soff[6];
#pragma unroll
    for (int i = 0; i < 6; i++) {
        int c = tid + i * 256;
        if (c < 1024) {
            const __nv_bfloat16* base = (c < 512) ? Ah : Al;
            int local = c & 511;
            int row = local >> 2, sub = local & 3;
            gp[i] = base + (size_t)(m0 + row) * K + sub * 8;
            adv[i] = 32;
            soff[i] = (uint32_t)((((c < 512) ? O_AH : O_AL) + row * TPITCH + sub * 8) * 2);
        } else {
            int local = c - 1024;                     // 0..511
            const __nv_bfloat16* base = (local < 256) ? Bh : Bl;
            int idx = local & 255;
            int krow = idx >> 3, sub = idx & 7;
            gp[i] = base + (size_t)krow * N + n0 + sub * 8;
            adv[i] = (size_t)32 * N;
            soff[i] = (uint32_t)((((local < 256) ? O_BH : O_BL) + krow * BPITCH + sub * 8) * 2);
        }
    }

#define LOAD_STAGE(s_) do { \
    uint32_t sb_ = smbase + (uint32_t)(((s_) % 3) * STAGE_E * 2); \
    _Pragma("unroll") \
    for (int i_ = 0; i_ < 6; i_++) \
        cp16(sb_ + soff[i_], gp[i_] + (size_t)(s_) * adv[i_]); \
    asm volatile("cp.async.commit_group;" ::: "memory"); \
} while (0)

    const int S = K / 32;
    LOAD_STAGE(0);
    LOAD_STAGE(1);

    float acc[2][4][4];
#pragma unroll
    for (int t = 0; t < 2; t++)
#pragma unroll
        for (int n = 0; n < 4; n++)
#pragma unroll
            for (int e = 0; e < 4; e++) acc[t][n][e] = 0.f;

    for (int s = 0; s < S; s++) {
        asm volatile("cp.async.wait_group 1;" ::: "memory");
        __syncthreads();
        if (s + 2 < S) { LOAD_STAGE(s + 2); }
        else { asm volatile("cp.async.commit_group;" ::: "memory"); }

        const uint32_t stg = smbase + (uint32_t)((s % 3) * STAGE_E * 2);

#pragma unroll
        for (int kk = 0; kk < 32; kk += 16) {
            uint32_t ah[2][4], al[2][4], bh[4][2], bl[4][2];
#pragma unroll
            for (int t = 0; t < 2; t++) {
                uint32_t off = aoff + (uint32_t)((t * 16 * TPITCH + kk) * 2);
                ldm_x4(ah[t][0], ah[t][1], ah[t][2], ah[t][3], stg + O_AH * 2 + off);
                ldm_x4(al[t][0], al[t][1], al[t][2], al[t][3], stg + O_AL * 2 + off);
            }
#pragma unroll
            for (int j = 0; j < 2; j++) {
                uint32_t boff = (uint32_t)((((kk + bko) * BPITCH) + bno + j * 16) * 2);
                ldm_x4t(bh[2*j][0], bh[2*j][1], bh[2*j+1][0], bh[2*j+1][1],
                        stg + O_BH * 2 + boff);
                ldm_x4t(bl[2*j][0], bl[2*j][1], bl[2*j+1][0], bl[2*j+1][1],
                        stg + O_BL * 2 + boff);
            }
#pragma unroll
            for (int t = 0; t < 2; t++)
#pragma unroll
                for (int n = 0; n < 4; n++) {
                    mma_bf16(acc[t][n], ah[t][0], ah[t][1], ah[t][2], ah[t][3],
                             bh[n][0], bh[n][1]);
                    mma_bf16(acc[t][n], ah[t][0], ah[t][1], ah[t][2], ah[t][3],
                             bl[n][0], bl[n][1]);
                    mma_bf16(acc[t][n], al[t][0], al[t][1], al[t][2], al[t][3],
                             bh[n][0], bh[n][1]);
                }
        }
    }

    // Epilogue
#pragma unroll
    for (int t = 0; t < 2; t++) {
#pragma unroll
        for (int half = 0; half < 2; half++) {
            int grow = m0 + wm * 32 + t * 16 + gr + half * 8;
            int orow = (flags & 4) ? ((grow >> 6) * SEQ + map_base + (grow & 63)) : grow;
            float* crow = C + (size_t)orow * N;
#pragma unroll
            for (int n = 0; n < 4; n++) {
                int col = n0 + wn * 32 + n * 8 + qc * 2;
                float2 v;
                v.x = acc[t][n][half * 2 + 0];
                v.y = acc[t][n][half * 2 + 1];
                if (flags & 2) {
                    float2 b2 = *reinterpret_cast<const float2*>(bias + col);
                    v.x += b2.x; v.y += b2.y;
                }
                if (flags & 1) {
                    float2 o = *reinterpret_cast<const float2*>(crow + col);
                    v.x += o.x; v.y += o.y;
                }
                *reinterpret_cast<float2*>(crow + col) = v;
            }
        }
    }
#undef LOAD_STAGE
}

// ---------------- streaming split: src[K,N] fp32 -> bf16 hi/lo [K,*] --------
// out row stride OS, column offset CO (for QKV/GU fusion). Pure streaming.
__global__ void split_strided_kernel(
    const float* __restrict__ src,
    __nv_bfloat16* __restrict__ hi, __nv_bfloat16* __restrict__ lo,
    int N, int OS, int CO, size_t total4)
{
    size_t i4 = (size_t)blockIdx.x * blockDim.x + threadIdx.x;
    if (i4 >= total4) return;
    int N4 = N >> 2;
    size_t k = i4 / N4;
    int j = (int)(i4 - k * N4);
    float4 v = reinterpret_cast<const float4*>(src)[i4];
    size_t o = k * OS + CO + 4 * (size_t)j;
    __nv_bfloat16 h0, l0, h1, l1, h2, l2, h3, l3;
    split_bf(v.x, h0, l0); split_bf(v.y, h1, l1);
    split_bf(v.z, h2, l2); split_bf(v.w, h3, l3);
    *reinterpret_cast<__nv_bfloat162*>(hi + o)     = __nv_bfloat162(h0, h1);
    *reinterpret_cast<__nv_bfloat162*>(hi + o + 2) = __nv_bfloat162(h2, h3);
    *reinterpret_cast<__nv_bfloat162*>(lo + o)     = __nv_bfloat162(l0, l1);
    *reinterpret_cast<__nv_bfloat162*>(lo + o + 2) = __nv_bfloat162(l2, l3);
}

__global__ void split_kernel(const float* __restrict__ src,
                             __nv_bfloat16* __restrict__ hi,
                             __nv_bfloat16* __restrict__ lo, size_t n)
{
    size_t idx = (size_t)blockIdx.x * blockDim.x + threadIdx.x;
    if (idx >= n) return;
    __nv_bfloat16 h, l;
    split_bf(src[idx], h, l);
    hi[idx] = h; lo[idx] = l;
}

__global__ void rope_table_kernel(float* __restrict__ cosb, float* __restrict__ sinb)
{
    int idx = blockIdx.x * blockDim.x + threadIdx.x;
    if (idx >= SEQ * 64) return;
    int s = idx >> 6, i = idx & 63;
    double inv = exp(-((double)(2 * i) / 128.0) * log(10000.0));
    double ang = (double)s * inv;
    cosb[idx] = (float)cos(ang);
    sinb[idx] = (float)sin(ang);
}

__global__ void embed_gather_kernel(const int* __restrict__ ids,
                                    const float* __restrict__ table,
                                    float* __restrict__ h)
{
    int idx = blockIdx.x * blockDim.x + threadIdx.x;
    if (idx >= B_ * SP * DLLM) return;
    int d = idx & (DLLM - 1);
    int r = (idx >> 12) & (SP - 1);
    int b = idx >> 19;
    int id = ids[b * SP + r];
    h[((size_t)(b * SEQ + r)) * DLLM + d] = table[(size_t)id * DLLM + d];
}

__global__ __launch_bounds__(256) void rmsnorm_kernel(
    const float* __restrict__ x, const float* __restrict__ w, float* __restrict__ out)
{
    int t = blockIdx.x;
    const float4* xr = reinterpret_cast<const float4*>(x + (size_t)t * DLLM);
    float4 vals[4];
    float s = 0.f;
#pragma unroll
    for (int j = 0; j < 4; j++) {
        float4 v = xr[threadIdx.x + j * 256];
        vals[j] = v;
        s += v.x * v.x + v.y * v.y + v.z * v.z + v.w * v.w;
    }
#pragma unroll
    for (int off = 16; off > 0; off >>= 1) s += __shfl_xor_sync(0xffffffffu, s, off);
    __shared__ float red[8];
    __shared__ float sscale;
    if ((threadIdx.x & 31) == 0) red[threadIdx.x >> 5] = s;
    __syncthreads();
    if (threadIdx.x == 0) {
        float r = 0.f;
#pragma unroll
        for (int i = 0; i < 8; i++) r += red[i];
        sscale = rsqrtf(r * (1.0f / DLLM) + EPS);
    }
    __syncthreads();
    float sc = sscale;
    const float4* w4 = reinterpret_cast<const float4*>(w);
    float4* o4 = reinterpret_cast<float4*>(out + (size_t)t * DLLM);
#pragma unroll
    for (int j = 0; j < 4; j++) {
        float4 v = vals[j];
        float4 wv = w4[threadIdx.x + j * 256];
        o4[threadIdx.x + j * 256] = make_float4(
            v.x * sc * wv.x, v.y * sc * wv.y, v.z * sc * wv.z, v.w * sc * wv.w);
    }
}

__global__ __launch_bounds__(256) void rmsnorm_split_kernel(
    const float* __restrict__ x, const float* __restrict__ w,
    __nv_bfloat16* __restrict__ ohi, __nv_bfloat16* __restrict__ olo)
{
    int t = blockIdx.x;
    const float4* xr = reinterpret_cast<const float4*>(x + (size_t)t * DLLM);
    float4 vals[4];
    float s = 0.f;
#pragma unroll
    for (int j = 0; j < 4; j++) {
        float4 v = xr[threadIdx.x + j * 256];
        vals[j] = v;
        s += v.x * v.x + v.y * v.y + v.z * v.z + v.w * v.w;
    }
#pragma unroll
    for (int off = 16; off > 0; off >>= 1) s += __shfl_xor_sync(0xffffffffu, s, off);
    __shared__ float red[8];
    __shared__ float sscale;
    if ((threadIdx.x & 31) == 0) red[threadIdx.x >> 5] = s;
    __syncthreads();
    if (threadIdx.x == 0) {
        float r = 0.f;
#pragma unroll
        for (int i = 0; i < 8; i++) r += red[i];
        sscale = rsqrtf(r * (1.0f / DLLM) + EPS);
    }
    __syncthreads();
    float sc = sscale;
    const float4* w4 = reinterpret_cast<const float4*>(w);
    size_t base = (size_t)t * DLLM;
#pragma unroll
    for (int j = 0; j < 4; j++) {
        float4 v = vals[j];
        float4 wv = w4[threadIdx.x + j * 256];
        float rr[4] = { v.x * sc * wv.x, v.y * sc * wv.y, v.z * sc * wv.z, v.w * sc * wv.w };
        size_t o = base + ((size_t)threadIdx.x + j * 256) * 4;
#pragma unroll
        for (int e = 0; e < 4; e++) {
            __nv_bfloat16 h, l;
            split_bf(rr[e], h, l);
            ohi[o + e] = h; olo[o + e] = l;
        }
    }
}

__global__ void rope_apply_kernel(float* __restrict__ qkv,
                                  const float* __restrict__ cosb,
                                  const float* __restrict__ sinb)
{
    int idx = blockIdx.x * blockDim.x + threadIdx.x;
    if (idx >= NTOK * NH * 64) return;
    int i = idx & 63;
    int h = (idx >> 6) & (NH - 1);
    int t = idx >> 11;
    int s = t & (SEQ - 1);
    float c = cosb[s * 64 + i];
    float sn = sinb[s * 64 + i];
    size_t base = (size_t)t * QKVS + h * HD + i;
    float x1 = qkv[base], x2 = qkv[base + 64];
    qkv[base]      = x1 * c - x2 * sn;
    qkv[base + 64] = x2 * c + x1 * sn;
    size_t kb = base + DLLM;
    x1 = qkv[kb]; x2 = qkv[kb + 64];
    qkv[kb]      = x1 * c - x2 * sn;
    qkv[kb + 64] = x2 * c + x1 * sn;
}

__global__ __launch_bounds__(256) void attention_kernel(
    const float* __restrict__ qkv,
    __nv_bfloat16* __restrict__ ohi, __nv_bfloat16* __restrict__ olo)
{
    __shared__ float sc[8][SEQ];
    const int b = blockIdx.z, hh = blockIdx.y;
    const int w = threadIdx.x >> 5, lane = threadIdx.x & 31;
    const int qi = blockIdx.x * 8 + w;
    const float scale = 0.088388347648318447f;

    const float* qrow = qkv + (size_t)(b * SEQ + qi) * QKVS + hh * HD;
    float4 qv = reinterpret_cast<const float4*>(qrow)[lane];

    const float* kbase = qkv + (size_t)b * SEQ * QKVS + DLLM + hh * HD;
    for (int kk = 0; kk <= qi; kk++) {
        float4 kv = reinterpret_cast<const float4*>(kbase + (size_t)kk * QKVS)[lane];
        float d = qv.x * kv.x + qv.y * kv.y + qv.z * kv.z + qv.w * kv.w;
#pragma unroll
        for (int off = 16; off > 0; off >>= 1) d += __shfl_xor_sync(0xffffffffu, d, off);
        if (lane == 0) sc[w][kk] = d * scale;
    }
    __syncwarp();

    float m = -1e30f;
    for (int kk = lane; kk <= qi; kk += 32) m = fmaxf(m, sc[w][kk]);
#pragma unroll
    for (int off = 16; off > 0; off >>= 1) m = fmaxf(m, __shfl_xor_sync(0xffffffffu, m, off));

    float ssum = 0.f;
    for (int kk = lane; kk <= qi; kk += 32) {
        float p = expf(sc[w][kk] - m);
        sc[w][kk] = p;
        ssum += p;
    }
#pragma unroll
    for (int off = 16; off > 0; off >>= 1) ssum += __shfl_xor_sync(0xffffffffu, ssum, off);
    __syncwarp();
    float inv = 1.0f / ssum;

    const float* vbase = qkv + (size_t)b * SEQ * QKVS + 2 * DLLM + hh * HD;
    float4 acc = make_float4(0.f, 0.f, 0.f, 0.f);
    for (int kk = 0; kk <= qi; kk++) {
        float p = sc[w][kk];
        float4 vv = reinterpret_cast<const float4*>(vbase + (size_t)kk * QKVS)[lane];
        acc.x += p * vv.x; acc.y += p * vv.y;
        acc.z += p * vv.z; acc.w += p * vv.w;
    }
    size_t o = (size_t)(b * SEQ + qi) * DLLM + hh * HD + lane * 4;
    float r[4] = { acc.x * inv, acc.y * inv, acc.z * inv, acc.w * inv };
#pragma unroll
    for (int e = 0; e < 4; e++) {
        __nv_bfloat16 h, l;
        split_bf(r[e], h, l);
        ohi[o + e] = h; olo[o + e] = l;
    }
}

__global__ void silu_mul_split_kernel(const float* __restrict__ gu,
                                      __nv_bfloat16* __restrict__ ohi,
                                      __nv_bfloat16* __restrict__ olo)
{
    int j = blockIdx.x * 256 + threadIdx.x;
    int t = blockIdx.y;
    const float* row = gu + (size_t)t * GUS;
    float x = row[j];
    float r = (x / (1.0f + expf(-x))) * row[DFF + j];
    __nv_bfloat16 h, l;
    split_bf(r, h, l);
    size_t o = (size_t)t * DFF + j;
    ohi[o] = h; olo[o] = l;
}

__global__ void pool_kernel(const float* __restrict__ xn, float* __restrict__ pooled)
{
    int idx = blockIdx.x * blockDim.x + threadIdx.x;
    if (idx >= B_ * DLLM) return;
    int b = idx >> 12, d = idx & (DLLM - 1);
    float s = 0.f;
    for (int t = 0; t < SEQ; t++)
        s += xn[(size_t)(b * SEQ + t) * DLLM + d];
    pooled[idx] = s * (1.0f / SEQ);
}

__global__ void head1_kernel(const float* __restrict__ pooled,
                             const float* __restrict__ W,
                             const float* __restrict__ bias,
                             float* __restrict__ y1)
{
    int b = blockIdx.x, j = threadIdx.x;
    const float* p = pooled + (size_t)b * DLLM;
    float s = bias[j];
    for (int i = 0; i < DLLM; i++) s += p[i] * W[(size_t)i * 768 + j];
    y1[b * 768 + j] = s;
}

__global__ void head2_kernel(const float* __restrict__ y1,
                             const float* __restrict__ W,
                             const float* __restrict__ bias,
                             float* __restrict__ out)
{
    int b = blockIdx.x;
    float s = 0.f;
    for (int j = threadIdx.x; j < 768; j += 256) s += y1[b * 768 + j] * W[j];
#pragma unroll
    for (int off = 16; off > 0; off >>= 1) s += __shfl_xor_sync(0xffffffffu, s, off);
    __shared__ float red[8];
    if ((threadIdx.x & 31) == 0) red[threadIdx.x >> 5] = s;
    __syncthreads();
    if (threadIdx.x == 0) {
        float r = 0.f;
#pragma unroll
        for (int i = 0; i < 8; i++) r += red[i];
        out[b] = r + bias[0];
    }
}

// ---------------------------------------------------------------------------
static inline void launch_split_w(const float* src, __nv_bfloat16* hi, __nv_bfloat16* lo,
                                  int K, int N, int OS, int CO)
{
    size_t total4 = (size_t)K * N / 4;
    split_strided_kernel<<<(int)((total4 + 255) / 256), 256>>>(src, hi, lo, N, OS, CO, total4);
}

extern "C" void kernel_launch(void* const* d_in, const int* in_sizes, int n_in,
                              void* d_out, int out_size)
{
    const float* text  = (const float*)d_in[0];
    const float* vis   = (const float*)d_in[1];
    const int*   ids   = (const int*)  d_in[2];
    const float* inW   = (const float*)d_in[3];
    const float* inb   = (const float*)d_in[4];
    const float* etab  = (const float*)d_in[5];
    const float* Wq    = (const float*)d_in[6];
    const float* Wk    = (const float*)d_in[7];
    const float* Wv    = (const float*)d_in[8];
    const float* Wo    = (const float*)d_in[9];
    const float* ln1   = (const float*)d_in[10];
    const float* ln2   = (const float*)d_in[11];
    const float* Wg    = (const float*)d_in[12];
    const float* Wu    = (const float*)d_in[13];
    const float* Wd    = (const float*)d_in[14];
    const float* fnw   = (const float*)d_in[15];
    const float* o1W   = (const float*)d_in[16];
    const float* o1b   = (const float*)d_in[17];
    const float* o2W   = (const float*)d_in[18];
    const float* o2b   = (const float*)d_in[19];
    float* out = (float*)d_out;

    cudaFuncSetAttribute(gemm_tc, cudaFuncAttributeMaxDynamicSharedMemorySize,
                         GSMEM_BYTES);

    float* S = nullptr;
    cudaGetSymbolAddress((void**)&S, g_scratch);
    __nv_bfloat16* BS = nullptr;
    cudaGetSymbolAddress((void**)&BS, g_bf);

    float* h    = S + OFF_H;
    float* xn   = S + OFF_XN;
    float* qkv  = S + OFF_QKV;
    float* gu   = S + OFF_GU;
    float* cosb = S + OFF_COS;
    float* sinb = S + OFF_SIN;
    float* pooled = S + OFF_POOL;
    float* y1   = S + OFF_Y1;

    __nv_bfloat16 *xnh = BS + BO_XNH, *xnl = BS + BO_XNL;
    __nv_bfloat16 *ath = BS + BO_ATH, *atl = BS + BO_ATL;
    __nv_bfloat16 *gh  = BS + BO_GH,  *gl  = BS + BO_GL;
    __nv_bfloat16 *txh = BS + BO_TXH, *txl = BS + BO_TXL;
    __nv_bfloat16 *vxh = BS + BO_VXH, *vxl = BS + BO_VXL;
    __nv_bfloat16 *inwh = BS + BO_INWH, *inwl = BS + BO_INWL;

    rope_table_kernel<<<(SEQ * 64 + 255) / 256, 256>>>(cosb, sinb);

    // Streaming weight splits, [K,N] layout (no transpose).
    launch_split_w(inW, inwh, inwl, DMODEL, DLLM, DLLM, 0);
    for (int l = 0; l < 2; l++) {
        __nv_bfloat16* qkvh = BS + BO_QKVH + (size_t)l * 3 * W4;
        __nv_bfloat16* qkvl = BS + BO_QKVL + (size_t)l * 3 * W4;
        launch_split_w(Wq + (size_t)l * W4, qkvh, qkvl, DLLM, DLLM, QKVS, 0);
        launch_split_w(Wk + (size_t)l * W4, qkvh, qkvl, DLLM, DLLM, QKVS, DLLM);
        launch_split_w(Wv + (size_t)l * W4, qkvh, qkvl, DLLM, DLLM, QKVS, 2 * DLLM);
        launch_split_w(Wo + (size_t)l * W4, BS + BO_OH + (size_t)l * W4,
                       BS + BO_OL + (size_t)l * W4, DLLM, DLLM, DLLM, 0);
        __nv_bfloat16* guh = BS + BO_GUH + (size_t)l * 2 * WF;
        __nv_bfloat16* gul = BS + BO_GUL + (size_t)l * 2 * WF;
        launch_split_w(Wg + (size_t)l * WF, guh, gul, DLLM, DFF, GUS, 0);
        launch_split_w(Wu + (size_t)l * WF, guh, gul, DLLM, DFF, GUS, DFF);
        launch_split_w(Wd + (size_t)l * WF, BS + BO_DWH + (size_t)l * WF,
                       BS + BO_DWL + (size_t)l * WF, DFF, DLLM, DLLM, 0);
    }

    embed_gather_kernel<<<(B_ * SP * DLLM + 255) / 256, 256>>>(ids, etab, h);
    split_kernel<<<(int)((SZ_TV + 255) / 256), 256>>>(text, txh, txl, SZ_TV);
    split_kernel<<<(int)((SZ_TV + 255) / 256), 256>>>(vis, vxh, vxl, SZ_TV);
    gemm_tc<<<dim3(DLLM / 64, 512 / 128), 256, GSMEM_BYTES>>>(
        txh, txl, inwh, inwl, h, 512, DLLM, DMODEL, 2 | 4, inb, SP);
    gemm_tc<<<dim3(DLLM / 64, 512 / 128), 256, GSMEM_BYTES>>>(
        vxh, vxl, inwh, inwl, h, 512, DLLM, DMODEL, 2 | 4, inb, SP + ST);

    for (int l = 0; l < 2; l++) {
        rmsnorm_split_kernel<<<NTOK, 256>>>(h, ln1 + (size_t)l * DLLM, xnh, xnl);
        gemm_tc<<<dim3(QKVS / 64, NTOK / 128), 256, GSMEM_BYTES>>>(
            xnh, xnl, BS + BO_QKVH + (size_t)l * 3 * W4, BS + BO_QKVL + (size_t)l * 3 * W4,
            qkv, NTOK, QKVS, DLLM, 0, nullptr, 0);
        rope_apply_kernel<<<(NTOK * NH * 64 + 255) / 256, 256>>>(qkv, cosb, sinb);
        attention_kernel<<<dim3(SEQ / 8, NH, B_), 256>>>(qkv, ath, atl);
        gemm_tc<<<dim3(DLLM / 64, NTOK / 128), 256, GSMEM_BYTES>>>(
            ath, atl, BS + BO_OH + (size_t)l * W4, BS + BO_OL + (size_t)l * W4,
            h, NTOK, DLLM, DLLM, 1, nullptr, 0);

        rmsnorm_split_kernel<<<NTOK, 256>>>(h, ln2 + (size_t)l * DLLM, xnh, xnl);
        gemm_tc<<<dim3(GUS / 64, NTOK / 128), 256, GSMEM_BYTES>>>(
            xnh, xnl, BS + BO_GUH + (size_t)l * 2 * WF, BS + BO_GUL + (size_t)l * 2 * WF,
            gu, NTOK, GUS, DLLM, 0, nullptr, 0);
        silu_mul_split_kernel<<<dim3(DFF / 256, NTOK), 256>>>(gu, gh, gl);
        gemm_tc<<<dim3(DLLM / 64, NTOK / 128), 256, GSMEM_BYTES>>>(
            gh, gl, BS + BO_DWH + (size_t)l * WF, BS + BO_DWL + (size_t)l * WF,
            h, NTOK, DLLM, DFF, 1, nullptr, 0);
    }

    rmsnorm_kernel<<<NTOK, 256>>>(h, fnw, xn);
    pool_kernel<<<(B_ * DLLM + 255) / 256, 256>>>(xn, pooled);
    head1_kernel<<<B_, 768>>>(pooled, o1W, o1b, y1);
    head2_kernel<<<B_, 256>>>(y1, o2W, o2b, out);
}

// round 14
// speedup vs baseline: 1.0924x; 1.0136x over previous
#include <cuda_runtime.h>
#include <cuda_bf16.h>
#include <math.h>
#include <stdint.h>

#define B_    8
#define SP    128
#define ST    64
#define SV    64
#define SEQ   256
#define DMODEL 768
#define DLLM  4096
#define NH    32
#define HD    128
#define DFF   11008
#define NTOK  (B_*SEQ)
#define QKVS  (3*DLLM)
#define GUS   (2*DFF)
#define EPS   1e-5f

// ---------------- fp32 scratch ----------------
#define SZ_TOKD ((size_t)NTOK*DLLM)
#define SZ_FF   ((size_t)NTOK*DFF)
#define OFF_H    ((size_t)0)
#define OFF_XN   (SZ_TOKD)
#define OFF_QKV  (2*SZ_TOKD)
#define OFF_GU   (5*SZ_TOKD)
#define OFF_COS  (OFF_GU + 2*SZ_FF)
#define OFF_SIN  (OFF_COS + (size_t)SEQ*64)
#define OFF_POOL (OFF_SIN + (size_t)SEQ*64)
#define OFF_Y1   (OFF_POOL + (size_t)B_*DLLM)
#define SCRATCH_TOTAL (OFF_Y1 + (size_t)B_*768)
__device__ float g_scratch[SCRATCH_TOTAL];

// ---------------- bf16 scratch (weights [K,N] layout) ----------------
#define W4 ((size_t)DLLM*DLLM)
#define WF ((size_t)DLLM*DFF)
#define SZ_TV  ((size_t)512*DMODEL)
#define SZ_INW ((size_t)DMODEL*DLLM)
#define BO_XNH  ((size_t)0)
#define BO_XNL  (BO_XNH + SZ_TOKD)
#define BO_ATH  (BO_XNL + SZ_TOKD)
#define BO_ATL  (BO_ATH + SZ_TOKD)
#define BO_GH   (BO_ATL + SZ_TOKD)
#define BO_GL   (BO_GH + SZ_FF)
#define BO_TXH  (BO_GL + SZ_FF)
#define BO_TXL  (BO_TXH + SZ_TV)
#define BO_VXH  (BO_TXL + SZ_TV)
#define BO_VXL  (BO_VXH + SZ_TV)
#define BO_INWH (BO_VXL + SZ_TV)
#define BO_INWL (BO_INWH + SZ_INW)
#define BO_QKVH (BO_INWL + SZ_INW)
#define BO_QKVL (BO_QKVH + 6*W4)
#define BO_OH   (BO_QKVL + 6*W4)
#define BO_OL   (BO_OH + 2*W4)
#define BO_GUH  (BO_OL + 2*W4)
#define BO_GUL  (BO_GUH + 4*WF)
#define BO_DWH  (BO_GUL + 4*WF)
#define BO_DWL  (BO_DWH + 2*WF)
#define BF_TOTAL (BO_DWL + 2*WF)
__device__ __align__(256) __nv_bfloat16 g_bf[BF_TOTAL];

// ---------------- helpers ----------------
__device__ __forceinline__ uint32_t smem_u32(const void* p) {
    uint32_t a;
    asm("{ .reg .u64 t; cvta.to.shared.u64 t, %1; cvt.u32.u64 %0, t; }" : "=r"(a) : "l"(p));
    return a;
}
__device__ __forceinline__ void cp16(uint32_t d, const void* s) {
    asm volatile("cp.async.cg.shared.global [%0], [%1], 16;" :: "r"(d), "l"(s));
}
__device__ __forceinline__ void split_bf(float x, __nv_bfloat16& h, __nv_bfloat16& l) {
    h = __float2bfloat16_rn(x);
    l = __float2bfloat16_rn(x - __bfloat162float(h));
}
__device__ __forceinline__ void mma_bf16(float* c,
    uint32_t a0, uint32_t a1, uint32_t a2, uint32_t a3, uint32_t b0, uint32_t b1) {
    asm volatile(
        "mma.sync.aligned.m16n8k16.row.col.f32.bf16.bf16.f32 "
        "{%0,%1,%2,%3}, {%4,%5,%6,%7}, {%8,%9}, {%0,%1,%2,%3};"
        : "+f"(c[0]), "+f"(c[1]), "+f"(c[2]), "+f"(c[3])
        : "r"(a0), "r"(a1), "r"(a2), "r"(a3), "r"(b0), "r"(b1));
}
__device__ __forceinline__ void ldm_x4(uint32_t& r0, uint32_t& r1,
                                       uint32_t& r2, uint32_t& r3, uint32_t a) {
    asm volatile("ldmatrix.sync.aligned.m8n8.x4.shared.b16 {%0,%1,%2,%3}, [%4];"
        : "=r"(r0), "=r"(r1), "=r"(r2), "=r"(r3) : "r"(a));
}
__device__ __forceinline__ void ldm_x4t(uint32_t& r0, uint32_t& r1,
                                        uint32_t& r2, uint32_t& r3, uint32_t a) {
    asm volatile("ldmatrix.sync.aligned.m8n8.x4.trans.shared.b16 {%0,%1,%2,%3}, [%4];"
        : "=r"(r0), "=r"(r1), "=r"(r2), "=r"(r3) : "r"(a));
}

// ---------------------------------------------------------------------------
// bf16-split GEMM via mma.sync + ldmatrix (unchanged from R13).
// BM=128, BN=64, BK=32; B consumed [K,N] via ldmatrix.trans.
// ---------------------------------------------------------------------------
#define TPITCH 40
#define BPITCH 72
#define O_AH 0
#define O_AL (128*TPITCH)
#define O_BH (256*TPITCH)
#define O_BL (O_BH + 32*BPITCH)
#define STAGE_E (O_BH + 64*BPITCH)
#define GSMEM_BYTES (3*STAGE_E*2)

__global__ __launch_bounds__(256, 2) void gemm_tc(
    const __nv_bfloat16* __restrict__ Ah, const __nv_bfloat16* __restrict__ Al,
    const __nv_bfloat16* __restrict__ Bh, const __nv_bfloat16* __restrict__ Bl,
    float* __restrict__ C, int M, int N, int K,
    int flags, const float* __restrict__ bias, int map_base)
{
    extern __shared__ __nv_bfloat16 sm[];
    const int tid = threadIdx.x;
    const int wid = tid >> 5, lane = tid & 31;
    const int wm = wid & 3, wn = wid >> 2;
    const int m0 = blockIdx.y * 128, n0 = blockIdx.x * 64;
    const int gr = lane >> 2, qc = lane & 3;
    const uint32_t smbase = smem_u32(sm);

    const uint32_t aoff = (uint32_t)(((wm * 32 + (lane & 15)) * TPITCH + ((lane >> 4) << 3)) * 2);
    const int bko = ((lane >> 3) & 1) * 8 + (lane & 7);
    const int bno = wn * 32 + ((lane >> 4) << 3);

    const __nv_bfloat16* gp[6];
    size_t adv[6];
    uint32_t soff[6];
#pragma unroll
    for (int i = 0; i < 6; i++) {
        int c = tid + i * 256;
        if (c < 1024) {
            const __nv_bfloat16* base = (c < 512) ? Ah : Al;
            int local = c & 511;
            int row = local >> 2, sub = local & 3;
            gp[i] = base + (size_t)(m0 + row) * K + sub * 8;
            adv[i] = 32;
            soff[i] = (uint32_t)((((c < 512) ? O_AH : O_AL) + row * TPITCH + sub * 8) * 2);
        } else {
            int local = c - 1024;
            const __nv_bfloat16* base = (local < 256) ? Bh : Bl;
            int idx = local & 255;
            int krow = idx >> 3, sub = idx & 7;
            gp[i] = base + (size_t)krow * N + n0 + sub * 8;
            adv[i] = (size_t)32 * N;
            soff[i] = (uint32_t)((((local < 256) ? O_BH : O_BL) + krow * BPITCH + sub * 8) * 2);
        }
    }

#define LOAD_STAGE(s_) do { \
    uint32_t sb_ = smbase + (uint32_t)(((s_) % 3) * STAGE_E * 2); \
    _Pragma("unroll") \
    for (int i_ = 0; i_ < 6; i_++) \
        cp16(sb_ + soff[i_], gp[i_] + (size_t)(s_) * adv[i_]); \
    asm volatile("cp.async.commit_group;" ::: "memory"); \
} while (0)

    const int S = K / 32;
    LOAD_STAGE(0);
    LOAD_STAGE(1);

    float acc[2][4][4];
#pragma unroll
    for (int t = 0; t < 2; t++)
#pragma unroll
        for (int n = 0; n < 4; n++)
#pragma unroll
            for (int e = 0; e < 4; e++) acc[t][n][e] = 0.f;

    for (int s = 0; s < S; s++) {
        asm volatile("cp.async.wait_group 1;" ::: "memory");
        __syncthreads();
        if (s + 2 < S) { LOAD_STAGE(s + 2); }
        else { asm volatile("cp.async.commit_group;" ::: "memory"); }

        const uint32_t stg = smbase + (uint32_t)((s % 3) * STAGE_E * 2);

#pragma unroll
        for (int kk = 0; kk < 32; kk += 16) {
            uint32_t ah[2][4], al[2][4], bh[4][2], bl[4][2];
#pragma unroll
            for (int t = 0; t < 2; t++) {
                uint32_t off = aoff + (uint32_t)((t * 16 * TPITCH + kk) * 2);
                ldm_x4(ah[t][0], ah[t][1], ah[t][2], ah[t][3], stg + O_AH * 2 + off);
                ldm_x4(al[t][0], al[t][1], al[t][2], al[t][3], stg + O_AL * 2 + off);
            }
#pragma unroll
            for (int j = 0; j < 2; j++) {
                uint32_t boff = (uint32_t)((((kk + bko) * BPITCH) + bno + j * 16) * 2);
                ldm_x4t(bh[2*j][0], bh[2*j][1], bh[2*j+1][0], bh[2*j+1][1],
                        stg + O_BH * 2 + boff);
                ldm_x4t(bl[2*j][0], bl[2*j][1], bl[2*j+1][0], bl[2*j+1][1],
                        stg + O_BL * 2 + boff);
            }
#pragma unroll
            for (int t = 0; t < 2; t++)
#pragma unroll
                for (int n = 0; n < 4; n++) {
                    mma_bf16(acc[t][n], ah[t][0], ah[t][1], ah[t][2], ah[t][3],
                             bh[n][0], bh[n][1]);
                    mma_bf16(acc[t][n], ah[t][0], ah[t][1], ah[t][2], ah[t][3],
                             bl[n][0], bl[n][1]);
                    mma_bf16(acc[t][n], al[t][0], al[t][1], al[t][2], al[t][3],
                             bh[n][0], bh[n][1]);
                }
        }
    }

#pragma unroll
    for (int t = 0; t < 2; t++) {
#pragma unroll
        for (int half = 0; half < 2; half++) {
            int grow = m0 + wm * 32 + t * 16 + gr + half * 8;
            int orow = (flags & 4) ? ((grow >> 6) * SEQ + map_base + (grow & 63)) : grow;
            float* crow = C + (size_t)orow * N;
#pragma unroll
            for (int n = 0; n < 4; n++) {
                int col = n0 + wn * 32 + n * 8 + qc * 2;
                float2 v;
                v.x = acc[t][n][half * 2 + 0];
                v.y = acc[t][n][half * 2 + 1];
                if (flags & 2) {
                    float2 b2 = *reinterpret_cast<const float2*>(bias + col);
                    v.x += b2.x; v.y += b2.y;
                }
                if (flags & 1) {
                    float2 o = *reinterpret_cast<const float2*>(crow + col);
                    v.x += o.x; v.y += o.y;
                }
                *reinterpret_cast<float2*>(crow + col) = v;
            }
        }
    }
#undef LOAD_STAGE
}

// ---------------- streaming split: 8 elems/thread, 16B stores --------------
// src[K,N] fp32 -> bf16 hi/lo rows of stride OS with column offset CO.
// Requires N%8==0, OS%8==0, CO%8==0 (true for all uses).
__global__ void split_strided_kernel(
    const float* __restrict__ src,
    __nv_bfloat16* __restrict__ hi, __nv_bfloat16* __restrict__ lo,
    int N, int OS, int CO, size_t total8)
{
    size_t i8 = (size_t)blockIdx.x * blockDim.x + threadIdx.x;
    if (i8 >= total8) return;
    int N8 = N >> 3;
    size_t k = i8 / N8;
    int j = (int)(i8 - k * N8);
    const float4* s4 = reinterpret_cast<const float4*>(src) + i8 * 2;
    float4 v0 = s4[0], v1 = s4[1];
    __align__(16) __nv_bfloat16 hb[8], lb[8];
    split_bf(v0.x, hb[0], lb[0]); split_bf(v0.y, hb[1], lb[1]);
    split_bf(v0.z, hb[2], lb[2]); split_bf(v0.w, hb[3], lb[3]);
    split_bf(v1.x, hb[4], lb[4]); split_bf(v1.y, hb[5], lb[5]);
    split_bf(v1.z, hb[6], lb[6]); split_bf(v1.w, hb[7], lb[7]);
    size_t o = k * OS + CO + 8 * (size_t)j;
    *reinterpret_cast<uint4*>(hi + o) = *reinterpret_cast<uint4*>(hb);
    *reinterpret_cast<uint4*>(lo + o) = *reinterpret_cast<uint4*>(lb);
}

// contiguous split, 8 elems/thread, 16B stores (n%8==0)
__global__ void split_kernel(const float* __restrict__ src,
                             __nv_bfloat16* __restrict__ hi,
                             __nv_bfloat16* __restrict__ lo, size_t total8)
{
    size_t i8 = (size_t)blockIdx.x * blockDim.x + threadIdx.x;
    if (i8 >= total8) return;
    const float4* s4 = reinterpret_cast<const float4*>(src) + i8 * 2;
    float4 v0 = s4[0], v1 = s4[1];
    __align__(16) __nv_bfloat16 hb[8], lb[8];
    split_bf(v0.x, hb[0], lb[0]); split_bf(v0.y, hb[1], lb[1]);
    split_bf(v0.z, hb[2], lb[2]); split_bf(v0.w, hb[3], lb[3]);
    split_bf(v1.x, hb[4], lb[4]); split_bf(v1.y, hb[5], lb[5]);
    split_bf(v1.z, hb[6], lb[6]); split_bf(v1.w, hb[7], lb[7]);
    size_t o = i8 * 8;
    *reinterpret_cast<uint4*>(hi + o) = *reinterpret_cast<uint4*>(hb);
    *reinterpret_cast<uint4*>(lo + o) = *reinterpret_cast<uint4*>(lb);
}

__global__ void rope_table_kernel(float* __restrict__ cosb, float* __restrict__ sinb)
{
    int idx = blockIdx.x * blockDim.x + threadIdx.x;
    if (idx >= SEQ * 64) return;
    int s = idx >> 6, i = idx & 63;
    double inv = exp(-((double)(2 * i) / 128.0) * log(10000.0));
    double ang = (double)s * inv;
    cosb[idx] = (float)cos(ang);
    sinb[idx] = (float)sin(ang);
}

// float4 gather
__global__ void embed_gather_kernel(const int* __restrict__ ids,
                                    const float* __restrict__ table,
                                    float* __restrict__ h)
{
    int idx = blockIdx.x * blockDim.x + threadIdx.x;   // B_*SP*DLLM/4
    if (idx >= B_ * SP * (DLLM / 4)) return;
    int d4 = idx & (DLLM / 4 - 1);
    int r = (idx / (DLLM / 4)) & (SP - 1);
    int b = idx / (SP * DLLM / 4);
    int id = ids[b * SP + r];
    reinterpret_cast<float4*>(h + ((size_t)(b * SEQ + r)) * DLLM)[d4] =
        reinterpret_cast<const float4*>(table + (size_t)id * DLLM)[d4];
}

__global__ __launch_bounds__(256) void rmsnorm_kernel(
    const float* __restrict__ x, const float* __restrict__ w, float* __restrict__ out)
{
    int t = blockIdx.x;
    const float4* xr = reinterpret_cast<const float4*>(x + (size_t)t * DLLM);
    float4 vals[4];
    float s = 0.f;
#pragma unroll
    for (int j = 0; j < 4; j++) {
        float4 v = xr[threadIdx.x + j * 256];
        vals[j] = v;
        s += v.x * v.x + v.y * v.y + v.z * v.z + v.w * v.w;
    }
#pragma unroll
    for (int off = 16; off > 0; off >>= 1) s += __shfl_xor_sync(0xffffffffu, s, off);
    __shared__ float red[8];
    __shared__ float sscale;
    if ((threadIdx.x & 31) == 0) red[threadIdx.x >> 5] = s;
    __syncthreads();
    if (threadIdx.x == 0) {
        float r = 0.f;
#pragma unroll
        for (int i = 0; i < 8; i++) r += red[i];
        sscale = rsqrtf(r * (1.0f / DLLM) + EPS);
    }
    __syncthreads();
    float sc = sscale;
    const float4* w4 = reinterpret_cast<const float4*>(w);
    float4* o4 = reinterpret_cast<float4*>(out + (size_t)t * DLLM);
#pragma unroll
    for (int j = 0; j < 4; j++) {
        float4 v = vals[j];
        float4 wv = w4[threadIdx.x + j * 256];
        o4[threadIdx.x + j * 256] = make_float4(
            v.x * sc * wv.x, v.y * sc * wv.y, v.z * sc * wv.z, v.w * sc * wv.w);
    }
}

__global__ __launch_bounds__(256) void rmsnorm_split_kernel(
    const float* __restrict__ x, const float* __restrict__ w,
    __nv_bfloat16* __restrict__ ohi, __nv_bfloat16* __restrict__ olo)
{
    int t = blockIdx.x;
    const float4* xr = reinterpret_cast<const float4*>(x + (size_t)t * DLLM);
    float4 vals[4];
    float s = 0.f;
#pragma unroll
    for (int j = 0; j < 4; j++) {
        float4 v = xr[threadIdx.x + j * 256];
        vals[j] = v;
        s += v.x * v.x + v.y * v.y + v.z * v.z + v.w * v.w;
    }
#pragma unroll
    for (int off = 16; off > 0; off >>= 1) s += __shfl_xor_sync(0xffffffffu, s, off);
    __shared__ float red[8];
    __shared__ float sscale;
    if ((threadIdx.x & 31) == 0) red[threadIdx.x >> 5] = s;
    __syncthreads();
    if (threadIdx.x == 0) {
        float r = 0.f;
#pragma unroll
        for (int i = 0; i < 8; i++) r += red[i];
        sscale = rsqrtf(r * (1.0f / DLLM) + EPS);
    }
    __syncthreads();
    float sc = sscale;
    const float4* w4 = reinterpret_cast<const float4*>(w);
    size_t base = (size_t)t * DLLM;
#pragma unroll
    for (int j = 0; j < 4; j++) {
        float4 v = vals[j];
        float4 wv = w4[threadIdx.x + j * 256];
        float rr[4] = { v.x * sc * wv.x, v.y * sc * wv.y, v.z * sc * wv.z, v.w * sc * wv.w };
        size_t o = base + ((size_t)threadIdx.x + j * 256) * 4;
        __align__(8) __nv_bfloat16 hb[4], lb[4];
#pragma unroll
        for (int e = 0; e < 4; e++) split_bf(rr[e], hb[e], lb[e]);
        *reinterpret_cast<uint2*>(ohi + o) = *reinterpret_cast<uint2*>(hb);
        *reinterpret_cast<uint2*>(olo + o) = *reinterpret_cast<uint2*>(lb);
    }
}

__global__ void rope_apply_kernel(float* __restrict__ qkv,
                                  const float* __restrict__ cosb,
                                  const float* __restrict__ sinb)
{
    int idx = blockIdx.x * blockDim.x + threadIdx.x;
    if (idx >= NTOK * NH * 64) return;
    int i = idx & 63;
    int h = (idx >> 6) & (NH - 1);
    int t = idx >> 11;
    int s = t & (SEQ - 1);
    float c = cosb[s * 64 + i];
    float sn = sinb[s * 64 + i];
    size_t base = (size_t)t * QKVS + h * HD + i;
    float x1 = qkv[base], x2 = qkv[base + 64];
    qkv[base]      = x1 * c - x2 * sn;
    qkv[base + 64] = x2 * c + x1 * sn;
    size_t kb = base + DLLM;
    x1 = qkv[kb]; x2 = qkv[kb + 64];
    qkv[kb]      = x1 * c - x2 * sn;
    qkv[kb + 64] = x2 * c + x1 * sn;
}

__global__ __launch_bounds__(256) void attention_kernel(
    const float* __restrict__ qkv,
    __nv_bfloat16* __restrict__ ohi, __nv_bfloat16* __restrict__ olo)
{
    __shared__ float sc[8][SEQ];
    const int b = blockIdx.z, hh = blockIdx.y;
    const int w = threadIdx.x >> 5, lane = threadIdx.x & 31;
    const int qi = blockIdx.x * 8 + w;
    const float scale = 0.088388347648318447f;

    const float* qrow = qkv + (size_t)(b * SEQ + qi) * QKVS + hh * HD;
    float4 qv = reinterpret_cast<const float4*>(qrow)[lane];

    const float* kbase = qkv + (size_t)b * SEQ * QKVS + DLLM + hh * HD;
    for (int kk = 0; kk <= qi; kk++) {
        float4 kv = reinterpret_cast<const float4*>(kbase + (size_t)kk * QKVS)[lane];
        float d = qv.x * kv.x + qv.y * kv.y + qv.z * kv.z + qv.w * kv.w;
#pragma unroll
        for (int off = 16; off > 0; off >>= 1) d += __shfl_xor_sync(0xffffffffu, d, off);
        if (lane == 0) sc[w][kk] = d * scale;
    }
    __syncwarp();

    float m = -1e30f;
    for (int kk = lane; kk <= qi; kk += 32) m = fmaxf(m, sc[w][kk]);
#pragma unroll
    for (int off = 16; off > 0; off >>= 1) m = fmaxf(m, __shfl_xor_sync(0xffffffffu, m, off));

    float ssum = 0.f;
    for (int kk = lane; kk <= qi; kk += 32) {
        float p = expf(sc[w][kk] - m);
        sc[w][kk] = p;
        ssum += p;
    }
#pragma unroll
    for (int off = 16; off > 0; off >>= 1) ssum += __shfl_xor_sync(0xffffffffu, ssum, off);
    __syncwarp();
    float inv = 1.0f / ssum;

    const float* vbase = qkv + (size_t)b * SEQ * QKVS + 2 * DLLM + hh * HD;
    float4 acc = make_float4(0.f, 0.f, 0.f, 0.f);
    for (int kk = 0; kk <= qi; kk++) {
        float p = sc[w][kk];
        float4 vv = reinterpret_cast<const float4*>(vbase + (size_t)kk * QKVS)[lane];
        acc.x += p * vv.x; acc.y += p * vv.y;
        acc.z += p * vv.z; acc.w += p * vv.w;
    }
    size_t o = (size_t)(b * SEQ + qi) * DLLM + hh * HD + lane * 4;
    float r[4] = { acc.x * inv, acc.y * inv, acc.z * inv, acc.w * inv };
    __align__(8) __nv_bfloat16 hb[4], lb[4];
#pragma unroll
    for (int e = 0; e < 4; e++) split_bf(r[e], hb[e], lb[e]);
    *reinterpret_cast<uint2*>(ohi + o) = *reinterpret_cast<uint2*>(hb);
    *reinterpret_cast<uint2*>(olo + o) = *reinterpret_cast<uint2*>(lb);
}

// SwiGLU 8-wide: flat index over NTOK*DFF/8
__global__ void silu_mul_split_kernel(const float* __restrict__ gu,
                                      __nv_bfloat16* __restrict__ ohi,
                                      __nv_bfloat16* __restrict__ olo, size_t total8)
{
    size_t i8 = (size_t)blockIdx.x * blockDim.x + threadIdx.x;
    if (i8 >= total8) return;
    const int D8 = DFF / 8;
    size_t t = i8 / D8;
    int j = (int)(i8 - t * D8) * 8;
    const float* row = gu + t * GUS;
    const float4* g4 = reinterpret_cast<const float4*>(row + j);
    const float4* u4 = reinterpret_cast<const float4*>(row + DFF + j);
    float4 g0 = g4[0], g1 = g4[1];
    float4 u0 = u4[0], u1 = u4[1];
    float rr[8] = {
        (g0.x / (1.0f + expf(-g0.x))) * u0.x,
        (g0.y / (1.0f + expf(-g0.y))) * u0.y,
        (g0.z / (1.0f + expf(-g0.z))) * u0.z,
        (g0.w / (1.0f + expf(-g0.w))) * u0.w,
        (g1.x / (1.0f + expf(-g1.x))) * u1.x,
        (g1.y / (1.0f + expf(-g1.y))) * u1.y,
        (g1.z / (1.0f + expf(-g1.z))) * u1.z,
        (g1.w / (1.0f + expf(-g1.w))) * u1.w
    };
    __align__(16) __nv_bfloat16 hb[8], lb[8];
#pragma unroll
    for (int e = 0; e < 8; e++) split_bf(rr[e], hb[e], lb[e]);
    size_t o = t * DFF + j;
    *reinterpret_cast<uint4*>(ohi + o) = *reinterpret_cast<uint4*>(hb);
    *reinterpret_cast<uint4*>(olo + o) = *reinterpret_cast<uint4*>(lb);
}

__global__ void pool_kernel(const float* __restrict__ xn, float* __restrict__ pooled)
{
    int idx = blockIdx.x * blockDim.x + threadIdx.x;
    if (idx >= B_ * DLLM) return;
    int b = idx >> 12, d = idx & (DLLM - 1);
    float s = 0.f;
    for (int t = 0; t < SEQ; t++)
        s += xn[(size_t)(b * SEQ + t) * DLLM + d];
    pooled[idx] = s * (1.0f / SEQ);
}

__global__ void head1_kernel(const float* __restrict__ pooled,
                             const float* __restrict__ W,
                             const float* __restrict__ bias,
                             float* __restrict__ y1)
{
    int b = blockIdx.x, j = threadIdx.x;
    const float* p = pooled + (size_t)b * DLLM;
    float s = bias[j];
    for (int i = 0; i < DLLM; i++) s += p[i] * W[(size_t)i * 768 + j];
    y1[b * 768 + j] = s;
}

__global__ void head2_kernel(const float* __restrict__ y1,
                             const float* __restrict__ W,
                             const float* __restrict__ bias,
                             float* __restrict__ out)
{
    int b = blockIdx.x;
    float s = 0.f;
    for (int j = threadIdx.x; j < 768; j += 256) s += y1[b * 768 + j] * W[j];
#pragma unroll
    for (int off = 16; off > 0; off >>= 1) s += __shfl_xor_sync(0xffffffffu, s, off);
    __shared__ float red[8];
    if ((threadIdx.x & 31) == 0) red[threadIdx.x >> 5] = s;
    __syncthreads();
    if (threadIdx.x == 0) {
        float r = 0.f;
#pragma unroll
        for (int i = 0; i < 8; i++) r += red[i];
        out[b] = r + bias[0];
    }
}

// ---------------------------------------------------------------------------
static inline void launch_split_w(const float* src, __nv_bfloat16* hi, __nv_bfloat16* lo,
                                  int K, int N, int OS, int CO)
{
    size_t total8 = (size_t)K * N / 8;
    split_strided_kernel<<<(int)((total8 + 255) / 256), 256>>>(src, hi, lo, N, OS, CO, total8);
}

extern "C" void kernel_launch(void* const* d_in, const int* in_sizes, int n_in,
                              void* d_out, int out_size)
{
    const float* text  = (const float*)d_in[0];
    const float* vis   = (const float*)d_in[1];
    const int*   ids   = (const int*)  d_in[2];
    const float* inW   = (const float*)d_in[3];
    const float* inb   = (const float*)d_in[4];
    const float* etab  = (const float*)d_in[5];
    const float* Wq    = (const float*)d_in[6];
    const float* Wk    = (const float*)d_in[7];
    const float* Wv    = (const float*)d_in[8];
    const float* Wo    = (const float*)d_in[9];
    const float* ln1   = (const float*)d_in[10];
    const float* ln2   = (const float*)d_in[11];
    const float* Wg    = (const float*)d_in[12];
    const float* Wu    = (const float*)d_in[13];
    const float* Wd    = (const float*)d_in[14];
    const float* fnw   = (const float*)d_in[15];
    const float* o1W   = (const float*)d_in[16];
    const float* o1b   = (const float*)d_in[17];
    const float* o2W   = (const float*)d_in[18];
    const float* o2b   = (const float*)d_in[19];
    float* out = (float*)d_out;

    cudaFuncSetAttribute(gemm_tc, cudaFuncAttributeMaxDynamicSharedMemorySize,
                         GSMEM_BYTES);

    float* S = nullptr;
    cudaGetSymbolAddress((void**)&S, g_scratch);
    __nv_bfloat16* BS = nullptr;
    cudaGetSymbolAddress((void**)&BS, g_bf);

    float* h    = S + OFF_H;
    float* xn   = S + OFF_XN;
    float* qkv  = S + OFF_QKV;
    float* gu   = S + OFF_GU;
    float* cosb = S + OFF_COS;
    float* sinb = S + OFF_SIN;
    float* pooled = S + OFF_POOL;
    float* y1   = S + OFF_Y1;

    __nv_bfloat16 *xnh = BS + BO_XNH, *xnl = BS + BO_XNL;
    __nv_bfloat16 *ath = BS + BO_ATH, *atl = BS + BO_ATL;
    __nv_bfloat16 *gh  = BS + BO_GH,  *gl  = BS + BO_GL;
    __nv_bfloat16 *txh = BS + BO_TXH, *txl = BS + BO_TXL;
    __nv_bfloat16 *vxh = BS + BO_VXH, *vxl = BS + BO_VXL;
    __nv_bfloat16 *inwh = BS + BO_INWH, *inwl = BS + BO_INWL;

    rope_table_kernel<<<(SEQ * 64 + 255) / 256, 256>>>(cosb, sinb);

    launch_split_w(inW, inwh, inwl, DMODEL, DLLM, DLLM, 0);
    for (int l = 0; l < 2; l++) {
        __nv_bfloat16* qkvh = BS + BO_QKVH + (size_t)l * 3 * W4;
        __nv_bfloat16* qkvl = BS + BO_QKVL + (size_t)l * 3 * W4;
        launch_split_w(Wq + (size_t)l * W4, qkvh, qkvl, DLLM, DLLM, QKVS, 0);
        launch_split_w(Wk + (size_t)l * W4, qkvh, qkvl, DLLM, DLLM, QKVS, DLLM);
        launch_split_w(Wv + (size_t)l * W4, qkvh, qkvl, DLLM, DLLM, QKVS, 2 * DLLM);
        launch_split_w(Wo + (size_t)l * W4, BS + BO_OH + (size_t)l * W4,
                       BS + BO_OL + (size_t)l * W4, DLLM, DLLM, DLLM, 0);
        __nv_bfloat16* guh = BS + BO_GUH + (size_t)l * 2 * WF;
        __nv_bfloat16* gul = BS + BO_GUL + (size_t)l * 2 * WF;
        launch_split_w(Wg + (size_t)l * WF, guh, gul, DLLM, DFF, GUS, 0);
        launch_split_w(Wu + (size_t)l * WF, guh, gul, DLLM, DFF, GUS, DFF);
        launch_split_w(Wd + (size_t)l * WF, BS + BO_DWH + (size_t)l * WF,
                       BS + BO_DWL + (size_t)l * WF, DFF, DLLM, DLLM, 0);
    }

    embed_gather_kernel<<<(B_ * SP * (DLLM / 4) + 255) / 256, 256>>>(ids, etab, h);
    split_kernel<<<(int)((SZ_TV / 8 + 255) / 256), 256>>>(text, txh, txl, SZ_TV / 8);
    split_kernel<<<(int)((SZ_TV / 8 + 255) / 256), 256>>>(vis, vxh, vxl, SZ_TV / 8);
    gemm_tc<<<dim3(DLLM / 64, 512 / 128), 256, GSMEM_BYTES>>>(
        txh, txl, inwh, inwl, h, 512, DLLM, DMODEL, 2 | 4, inb, SP);
    gemm_tc<<<dim3(DLLM / 64, 512 / 128), 256, GSMEM_BYTES>>>(
        vxh, vxl, inwh, inwl, h, 512, DLLM, DMODEL, 2 | 4, inb, SP + ST);

    for (int l = 0; l < 2; l++) {
        rmsnorm_split_kernel<<<NTOK, 256>>>(h, ln1 + (size_t)l * DLLM, xnh, xnl);
        gemm_tc<<<dim3(QKVS / 64, NTOK / 128), 256, GSMEM_BYTES>>>(
            xnh, xnl, BS + BO_QKVH + (size_t)l * 3 * W4, BS + BO_QKVL + (size_t)l * 3 * W4,
            qkv, NTOK, QKVS, DLLM, 0, nullptr, 0);
        rope_apply_kernel<<<(NTOK * NH * 64 + 255) / 256, 256>>>(qkv, cosb, sinb);
        attention_kernel<<<dim3(SEQ / 8, NH, B_), 256>>>(qkv, ath, atl);
        gemm_tc<<<dim3(DLLM / 64, NTOK / 128), 256, GSMEM_BYTES>>>(
            ath, atl, BS + BO_OH + (size_t)l * W4, BS + BO_OL + (size_t)l * W4,
            h, NTOK, DLLM, DLLM, 1, nullptr, 0);

        rmsnorm_split_kernel<<<NTOK, 256>>>(h, ln2 + (size_t)l * DLLM, xnh, xnl);
        gemm_tc<<<dim3(GUS / 64, NTOK / 128), 256, GSMEM_BYTES>>>(
            xnh, xnl, BS + BO_GUH + (size_t)l * 2 * WF, BS + BO_GUL + (size_t)l * 2 * WF,
            gu, NTOK, GUS, DLLM, 0, nullptr, 0);
        {
            size_t total8 = (size_t)NTOK * DFF / 8;
            silu_mul_split_kernel<<<(int)((total8 + 255) / 256), 256>>>(gu, gh, gl, total8);
        }
        gemm_tc<<<dim3(DLLM / 64, NTOK / 128), 256, GSMEM_BYTES>>>(
            gh, gl, BS + BO_DWH + (size_t)l * WF, BS + BO_DWL + (size_t)l * WF,
            h, NTOK, DLLM, DFF, 1, nullptr, 0);
    }

    rmsnorm_kernel<<<NTOK, 256>>>(h, fnw, xn);
    pool_kernel<<<(B_ * DLLM + 255) / 256, 256>>>(xn, pooled);
    head1_kernel<<<B_, 768>>>(pooled, o1W, o1b, y1);
    head2_kernel<<<B_, 256>>>(y1, o2W, o2b, out);
}